// round 5
// baseline (speedup 1.0000x reference)
#include <cuda_runtime.h>

#define NBATCH 8
#define SEQ 2048
#define DM 512
#define NH 8
#define DKV 64
#define ROWS (NBATCH*SEQ)              // 16384

#define HID_ELEMS (ROWS*DM)            // 8388608
#define PB_ELEMS (NH*SEQ*SEQ)          // 33554432

// scratch (device globals: allocation-free per harness rules)
__device__ float g_q[HID_ELEMS];
__device__ float g_k[HID_ELEMS];
__device__ float g_v[HID_ELEMS];
__device__ float g_ctx[HID_ELEMS];
__device__ float g_bias[NH*4096];      // per-head bias LUT indexed by (k-q)+2047

// ---------------------------------------------------------------------------
// Relative-position bias LUT. Exact integer floor of the T5 bucket formula:
// large = 8 + floor(2*log2(a/8)) computed as 2e + (a*a >= 2^(2e+7)).
// ---------------------------------------------------------------------------
__global__ void bias_fill_kernel(const float* __restrict__ table,
                                 float* __restrict__ out_remain) {
    int idx = blockIdx.x * blockDim.x + threadIdx.x;
    if (idx < NH * 4096) {
        int h = idx >> 12;
        int ridx = idx & 4095;
        int rel = ridx - 2047;          // k - q
        int a = rel < 0 ? -rel : rel;
        int b;
        if (a < 8) {
            b = a;
        } else {
            int e = 28 - __clz(a);      // floor(log2(a)) - 3, a>=8 so e>=0
            long long aa = (long long)a * (long long)a;
            int v = 2 * e + ((aa >= (1LL << (2 * e + 7))) ? 1 : 0);
            b = 8 + v;
            if (b > 15) b = 15;
        }
        int bucket = (rel > 0 ? 16 : 0) + b;
        g_bias[idx] = table[bucket * NH + h];
    }
    if (out_remain != nullptr && idx < 8) out_remain[idx] = (float)idx;
}

// ---------------------------------------------------------------------------
// position_bias output: out[h][q][k] = LUT[h][k - q + 2047]
// ---------------------------------------------------------------------------
__global__ void pb_write_kernel(float* __restrict__ out_pb) {
    int q = blockIdx.x;
    int h = blockIdx.y;
    const float* brow = g_bias + h * 4096 + (2047 - q);
    float* dst = out_pb + ((size_t)(h * SEQ + q)) * SEQ;
    int t = threadIdx.x;
    #pragma unroll
    for (int it = 0; it < 2; it++) {
        int k4 = (t + it * 256) * 4;
        float4 v = make_float4(brow[k4], brow[k4 + 1], brow[k4 + 2], brow[k4 + 3]);
        *(float4*)&dst[k4] = v;
    }
}

// ---------------------------------------------------------------------------
// 64x64x32-tiled fp32 GEMM with OPTIONAL fused T5-RMS row scaling computed
// in-block: C[m][n] = rms(m) * sum_k (A[m][k]*lnw[k]) * W[k][n] (+resid[m][n])
// ---------------------------------------------------------------------------
__global__ void gemm64_kernel(const float* __restrict__ A, const float* __restrict__ W,
                              float* __restrict__ C,
                              const float* __restrict__ lnw,
                              int do_rms,
                              const float* __restrict__ resid) {
    __shared__ float sA[32 * 68];   // [k][m]  (also reused as sumsq partials)
    __shared__ float sB[32 * 68];   // [k][n]
    __shared__ float rowsq[64];
    int t = threadIdx.x;
    int tx = t & 15, ty = t >> 4;
    int m0 = blockIdx.y << 6;
    int n0 = blockIdx.x << 6;

    if (do_rms) {
        // per-row sum of squares over full k: 4 threads per row, 128 elems each
        int rr = t >> 2, pp = t & 3;
        const float* Ar = A + (size_t)(m0 + rr) * DM + pp * 128;
        float ss = 0.0f;
        #pragma unroll 8
        for (int kk = 0; kk < 128; kk += 4) {
            float4 v = *(const float4*)&Ar[kk];
            ss += v.x * v.x + v.y * v.y + v.z * v.z + v.w * v.w;
        }
        sA[rr * 4 + pp] = ss;     // reuse sA as partial buffer
        __syncthreads();
        if (t < 64) {
            float tot = sA[t * 4] + sA[t * 4 + 1] + sA[t * 4 + 2] + sA[t * 4 + 3];
            rowsq[t] = rsqrtf(tot * (1.0f / (float)DM) + 1e-6f);
        }
        __syncthreads();
    }

    float acc[4][4] = {};
    for (int k0 = 0; k0 < DM; k0 += 32) {
        #pragma unroll
        for (int it = 0; it < 2; it++) {
            int j = t + it * 256;            // 0..511 float4 slots
            int i = j >> 3;                  // A row 0..63
            int k4 = (j & 7) << 2;           // k offset 0..28
            float4 v = *(const float4*)&A[(size_t)(m0 + i) * DM + k0 + k4];
            if (lnw) {
                v.x *= lnw[k0 + k4 + 0]; v.y *= lnw[k0 + k4 + 1];
                v.z *= lnw[k0 + k4 + 2]; v.w *= lnw[k0 + k4 + 3];
            }
            sA[(k4 + 0) * 68 + i] = v.x;
            sA[(k4 + 1) * 68 + i] = v.y;
            sA[(k4 + 2) * 68 + i] = v.z;
            sA[(k4 + 3) * 68 + i] = v.w;
        }
        #pragma unroll
        for (int it = 0; it < 2; it++) {
            int j = t + it * 256;
            int kk = j >> 4;                 // 0..31
            int n4 = (j & 15) << 2;          // 0..60
            *(float4*)&sB[kk * 68 + n4] =
                *(const float4*)&W[(size_t)(k0 + kk) * DM + n0 + n4];
        }
        __syncthreads();
        #pragma unroll
        for (int kk = 0; kk < 32; kk++) {
            float4 a4 = *(float4*)&sA[kk * 68 + (ty << 2)];
            float4 b4 = *(float4*)&sB[kk * 68 + (tx << 2)];
            float ra[4] = {a4.x, a4.y, a4.z, a4.w};
            float rb[4] = {b4.x, b4.y, b4.z, b4.w};
            #pragma unroll
            for (int r = 0; r < 4; r++)
                #pragma unroll
                for (int c = 0; c < 4; c++)
                    acc[r][c] += ra[r] * rb[c];
        }
        __syncthreads();
    }
    #pragma unroll
    for (int r = 0; r < 4; r++) {
        int mrow = (ty << 2) + r;
        float sc = do_rms ? rowsq[mrow] : 1.0f;
        size_t off = (size_t)(m0 + mrow) * DM + n0 + (tx << 2);
        float4 o = make_float4(acc[r][0] * sc, acc[r][1] * sc,
                               acc[r][2] * sc, acc[r][3] * sc);
        if (resid) {
            float4 hv = *(const float4*)&resid[off];
            o.x += hv.x; o.y += hv.y; o.z += hv.z; o.w += hv.w;
        }
        *(float4*)&C[off] = o;
    }
}

// ---------------------------------------------------------------------------
// Flash attention: block = (n, h, 32 q-rows), 8 warps, warp w owns q-rows
// 4w..4w+3, lane c owns k-column c in the score phase and dims {2c,2c+1} in
// the PV phase. All pointers passed as parameters (real device addresses).
// ---------------------------------------------------------------------------
__global__ void attn_kernel(const float* __restrict__ Qbase,
                            const float* __restrict__ Kbase,
                            const float* __restrict__ Vbase,
                            float* __restrict__ Cbase,
                            const float* __restrict__ Bbase) {
    __shared__ float sQ[32 * 68];   // [qrow][d] pitch 68
    __shared__ float sK[32 * 68];   // [krow][d] pitch 68
    __shared__ float sV[32 * 68];   // [krow][d] pitch 68
    __shared__ float sP[32 * 33];   // [qrow][k] pitch 33 (scalar access only)
    __shared__ float sB[64];        // bias window: sB[c - qrow + 31]

    int t = threadIdx.x;
    int w = t >> 5;                 // warp 0..7
    int c = t & 31;                 // lane
    int q0 = blockIdx.x << 5;       // 32 q rows per block
    int h = blockIdx.y;
    int n = blockIdx.z;
    const float* Qg = Qbase + (size_t)n * SEQ * DM + h * DKV;
    const float* Kg = Kbase + (size_t)n * SEQ * DM + h * DKV;
    const float* Vg = Vbase + (size_t)n * SEQ * DM + h * DKV;
    const float* biasrow = Bbase + h * 4096;

    // load Q tile [32 x 64]
    #pragma unroll
    for (int it = 0; it < 2; it++) {
        int j = t + it * 256;            // 512 float4 slots
        int row = j >> 4;                // 0..31
        int d4 = (j & 15) << 2;          // 0..60
        *(float4*)&sQ[row * 68 + d4] = *(const float4*)&Qg[(size_t)(q0 + row) * DM + d4];
    }

    float2 o[4] = {};                    // dims 2c, 2c+1 for rows 4w..4w+3
    float mrow[4] = {-1e30f, -1e30f, -1e30f, -1e30f};
    float lrow[4] = {};

    for (int k0 = 0; k0 < SEQ; k0 += 32) {
        if (t < 64) sB[t] = biasrow[k0 - q0 + 2016 + t];
        #pragma unroll
        for (int it = 0; it < 2; it++) {
            int j = t + it * 256;
            int row = j >> 4;
            int d4 = (j & 15) << 2;
            *(float4*)&sK[row * 68 + d4] = *(const float4*)&Kg[(size_t)(k0 + row) * DM + d4];
            *(float4*)&sV[row * 68 + d4] = *(const float4*)&Vg[(size_t)(k0 + row) * DM + d4];
        }
        __syncthreads();

        // scores: lane c computes full dot(Q[row], K[c]) for rows 4w..4w+3
        float s[4] = {};
        #pragma unroll
        for (int d4 = 0; d4 < 64; d4 += 4) {
            float4 k4 = *(float4*)&sK[c * 68 + d4];
            #pragma unroll
            for (int r = 0; r < 4; r++) {
                float4 q4 = *(float4*)&sQ[(4 * w + r) * 68 + d4];  // broadcast
                s[r] += q4.x * k4.x + q4.y * k4.y + q4.z * k4.z + q4.w * k4.w;
            }
        }

        // bias + online softmax; all reductions full-warp (32 lanes = 32 kcols)
        #pragma unroll
        for (int r = 0; r < 4; r++) {
            s[r] += sB[c - (4 * w + r) + 31];
            float mx = s[r];
            #pragma unroll
            for (int off = 16; off > 0; off >>= 1)
                mx = fmaxf(mx, __shfl_xor_sync(0xffffffffu, mx, off));
            float mn = fmaxf(mrow[r], mx);
            float alpha = __expf(mrow[r] - mn);
            mrow[r] = mn;
            float p = __expf(s[r] - mn);
            float rs = p;
            #pragma unroll
            for (int off = 16; off > 0; off >>= 1)
                rs += __shfl_xor_sync(0xffffffffu, rs, off);
            lrow[r] = lrow[r] * alpha + rs;
            o[r].x *= alpha; o[r].y *= alpha;
            sP[(4 * w + r) * 33 + c] = p;
        }
        __syncwarp();   // sP rows 4w..4w+3 are warp-private

        // O += P V : lane c owns dims {2c, 2c+1}
        #pragma unroll 4
        for (int k = 0; k < 32; k++) {
            float2 v2 = *(float2*)&sV[k * 68 + 2 * c];
            #pragma unroll
            for (int r = 0; r < 4; r++) {
                float p = sP[(4 * w + r) * 33 + k];   // broadcast
                o[r].x += p * v2.x;
                o[r].y += p * v2.y;
            }
        }
        __syncthreads();   // all warps done reading sK/sV before next tile load
    }

    float* Cg = Cbase + (size_t)n * SEQ * DM + h * DKV;
    #pragma unroll
    for (int r = 0; r < 4; r++) {
        float inv = 1.0f / lrow[r];
        *(float2*)&Cg[(size_t)(q0 + 4 * w + r) * DM + 2 * c] =
            make_float2(o[r].x * inv, o[r].y * inv);
    }
}

// ---------------------------------------------------------------------------
extern "C" void kernel_launch(void* const* d_in, const int* in_sizes, int n_in,
                              void* d_out, int out_size) {
    const float* hidden = (const float*)d_in[0];
    const float* lnw    = (const float*)d_in[1];
    const float* wq     = (const float*)d_in[2];
    const float* wk     = (const float*)d_in[3];
    const float* wv     = (const float*)d_in[4];
    const float* wo     = (const float*)d_in[5];
    const float* table  = (const float*)d_in[6];
    float* out = (float*)d_out;

    // REAL device addresses of the __device__ scratch symbols.
    // (Passing g_q etc. directly from host passes the host shadow; on GB300
    //  ATS the GPU dereferences host memory silently -> q/k/v/ctx appeared
    //  zero on the device. This was the 0.6037459 bug in rounds 1/2/4.)
    float *pq, *pk, *pv, *pctx, *pbias;
    cudaGetSymbolAddress((void**)&pq,    g_q);
    cudaGetSymbolAddress((void**)&pk,    g_k);
    cudaGetSymbolAddress((void**)&pv,    g_v);
    cudaGetSymbolAddress((void**)&pctx,  g_ctx);
    cudaGetSymbolAddress((void**)&pbias, g_bias);

    bool full = out_size >= (HID_ELEMS + PB_ELEMS + 8);
    float* out_pb     = out + HID_ELEMS;
    float* out_remain = out + HID_ELEMS + PB_ELEMS;

    bias_fill_kernel<<<128, 256>>>(table, full ? out_remain : nullptr);
    if (full) pb_write_kernel<<<dim3(SEQ, NH), 256>>>(out_pb);

    dim3 gg(DM / 64, ROWS / 64);
    gemm64_kernel<<<gg, 256>>>(hidden, wq, pq, lnw, 1, nullptr);
    gemm64_kernel<<<gg, 256>>>(hidden, wk, pk, lnw, 1, nullptr);
    gemm64_kernel<<<gg, 256>>>(hidden, wv, pv, lnw, 1, nullptr);

    attn_kernel<<<dim3(SEQ / 32, NH, NBATCH), 256>>>(pq, pk, pv, pctx, pbias);

    gemm64_kernel<<<gg, 256>>>(pctx, wo, out, nullptr, 0, hidden);
}

// round 6
// speedup vs baseline: 1.2149x; 1.2149x over previous
#include <cuda_runtime.h>
#include <cuda_bf16.h>

#define NBATCH 8
#define SEQ 2048
#define DM 512
#define NH 8
#define DKV 64
#define ROWS (NBATCH*SEQ)              // 16384

#define HID_ELEMS (ROWS*DM)            // 8388608
#define PB_ELEMS (NH*SEQ*SEQ)          // 33554432
#define WELEMS (DM*DM)                 // 262144

// scratch (device globals: allocation-free per harness rules)
__device__ float g_qkv[3*HID_ELEMS];   // q | k | v
__device__ float g_ctx[HID_ELEMS];
__device__ float g_bias[NH*4096];      // per-head bias LUT indexed by (k-q)+2047
__device__ __nv_bfloat16 g_ahi[HID_ELEMS];   // split activations (normed, then ctx)
__device__ __nv_bfloat16 g_alo[HID_ELEMS];
__device__ __nv_bfloat16 g_whi[4*WELEMS];    // wq|wk|wv|wo hi
__device__ __nv_bfloat16 g_wlo[4*WELEMS];    // lo

// ---------------------------------------------------------------------------
// helpers
// ---------------------------------------------------------------------------
__device__ __forceinline__ unsigned smem_u32(const void* p) {
    unsigned a;
    asm("{ .reg .u64 t; cvta.to.shared.u64 t, %1; cvt.u32.u64 %0, t; }" : "=r"(a) : "l"(p));
    return a;
}
__device__ __forceinline__ void ldsm4(unsigned* r, unsigned addr) {
    asm volatile("ldmatrix.sync.aligned.m8n8.x4.shared.b16 {%0,%1,%2,%3}, [%4];"
        : "=r"(r[0]), "=r"(r[1]), "=r"(r[2]), "=r"(r[3]) : "r"(addr));
}
__device__ __forceinline__ void ldsm4t(unsigned* r, unsigned addr) {
    asm volatile("ldmatrix.sync.aligned.m8n8.x4.trans.shared.b16 {%0,%1,%2,%3}, [%4];"
        : "=r"(r[0]), "=r"(r[1]), "=r"(r[2]), "=r"(r[3]) : "r"(addr));
}
__device__ __forceinline__ void mma16816(float* c, const unsigned* a, unsigned b0, unsigned b1) {
    asm volatile("mma.sync.aligned.m16n8k16.row.col.f32.bf16.bf16.f32 "
        "{%0,%1,%2,%3}, {%4,%5,%6,%7}, {%8,%9}, {%0,%1,%2,%3};"
        : "+f"(c[0]), "+f"(c[1]), "+f"(c[2]), "+f"(c[3])
        : "r"(a[0]), "r"(a[1]), "r"(a[2]), "r"(a[3]), "r"(b0), "r"(b1));
}
__device__ __forceinline__ unsigned pack_bf16x2(float a, float b) {
    unsigned sa = __bfloat16_as_ushort(__float2bfloat16(a));
    unsigned sb = __bfloat16_as_ushort(__float2bfloat16(b));
    return sa | (sb << 16);
}

// ---------------------------------------------------------------------------
// Relative-position bias LUT (exact integer floor of T5 bucket formula)
// ---------------------------------------------------------------------------
__global__ void bias_fill_kernel(const float* __restrict__ table,
                                 float* __restrict__ out_remain) {
    int idx = blockIdx.x * blockDim.x + threadIdx.x;
    if (idx < NH * 4096) {
        int h = idx >> 12;
        int rel = (idx & 4095) - 2047;      // k - q
        int a = rel < 0 ? -rel : rel;
        int b;
        if (a < 8) {
            b = a;
        } else {
            int e = 28 - __clz(a);
            long long aa = (long long)a * (long long)a;
            int v = 2 * e + ((aa >= (1LL << (2 * e + 7))) ? 1 : 0);
            b = 8 + v;
            if (b > 15) b = 15;
        }
        int bucket = (rel > 0 ? 16 : 0) + b;
        g_bias[idx] = table[bucket * NH + h];
    }
    if (out_remain != nullptr && idx < 8) out_remain[idx] = (float)idx;
}

__global__ void pb_write_kernel(float* __restrict__ out_pb) {
    int q = blockIdx.x, h = blockIdx.y;
    const float* brow = g_bias + h * 4096 + (2047 - q);
    float* dst = out_pb + ((size_t)(h * SEQ + q)) * SEQ;
    int t = threadIdx.x;
    #pragma unroll
    for (int it = 0; it < 2; it++) {
        int k4 = (t + it * 256) * 4;
        float4 v = make_float4(brow[k4], brow[k4+1], brow[k4+2], brow[k4+3]);
        *(float4*)&dst[k4] = v;
    }
}

// ---------------------------------------------------------------------------
// Weight split: whi = bf16(w), wlo = bf16(w - whi), 4 matrices
// ---------------------------------------------------------------------------
__global__ void split_w_kernel(const float* __restrict__ wq, const float* __restrict__ wk,
                               const float* __restrict__ wv, const float* __restrict__ wo) {
    int idx = blockIdx.x * 256 + threadIdx.x;   // 0 .. 4*WELEMS-1
    const float* src = (idx < WELEMS) ? wq : (idx < 2*WELEMS) ? wk : (idx < 3*WELEMS) ? wv : wo;
    float x = src[idx & (WELEMS - 1)];
    __nv_bfloat16 h = __float2bfloat16(x);
    g_whi[idx] = h;
    g_wlo[idx] = __float2bfloat16(x - __bfloat162float(h));
}

// ---------------------------------------------------------------------------
// Activation split with fused T5 RMS + ln weight:
//   a[m][k] = hidden[m][k] * lnw[k] * rsqrt(mean(hidden[m]^2)+eps) -> hi/lo bf16
// ---------------------------------------------------------------------------
__global__ void split_a_kernel(const float* __restrict__ hidden, const float* __restrict__ lnw) {
    int m = blockIdx.x, t = threadIdx.x;   // 128 threads, 4 floats each
    float4 v = *(const float4*)&hidden[(size_t)m * DM + t * 4];
    float s = v.x*v.x + v.y*v.y + v.z*v.z + v.w*v.w;
    #pragma unroll
    for (int off = 16; off > 0; off >>= 1) s += __shfl_xor_sync(0xffffffffu, s, off);
    __shared__ float ws[4];
    if ((t & 31) == 0) ws[t >> 5] = s;
    __syncthreads();
    float rms = rsqrtf((ws[0]+ws[1]+ws[2]+ws[3]) * (1.0f/(float)DM) + 1e-6f);
    float4 l = *(const float4*)&lnw[t * 4];
    float a0 = v.x * l.x * rms, a1 = v.y * l.y * rms;
    float a2 = v.z * l.z * rms, a3 = v.w * l.w * rms;
    float h0 = __bfloat162float(__float2bfloat16(a0));
    float h1 = __bfloat162float(__float2bfloat16(a1));
    float h2 = __bfloat162float(__float2bfloat16(a2));
    float h3 = __bfloat162float(__float2bfloat16(a3));
    uint2 ph = make_uint2(pack_bf16x2(a0, a1), pack_bf16x2(a2, a3));
    uint2 pl = make_uint2(pack_bf16x2(a0-h0, a1-h1), pack_bf16x2(a2-h2, a3-h3));
    *(uint2*)&g_ahi[(size_t)m * DM + t * 4] = ph;
    *(uint2*)&g_alo[(size_t)m * DM + t * 4] = pl;
}

// ctx split (no rms/lnw), reuses g_ahi/g_alo
__global__ void split_ctx_kernel(const float* __restrict__ ctx) {
    int i4 = (blockIdx.x * 256 + threadIdx.x) * 4;
    float4 v = *(const float4*)&ctx[i4];
    float h0 = __bfloat162float(__float2bfloat16(v.x));
    float h1 = __bfloat162float(__float2bfloat16(v.y));
    float h2 = __bfloat162float(__float2bfloat16(v.z));
    float h3 = __bfloat162float(__float2bfloat16(v.w));
    *(uint2*)&g_ahi[i4] = make_uint2(pack_bf16x2(v.x, v.y), pack_bf16x2(v.z, v.w));
    *(uint2*)&g_alo[i4] = make_uint2(pack_bf16x2(v.x-h0, v.y-h1), pack_bf16x2(v.z-h2, v.w-h3));
}

// ---------------------------------------------------------------------------
// bf16x3 tensor-core GEMM: D = Ahi*(Whi+Wlo) + Alo*Whi (+resid), fp32 out.
// CTA tile 128m x 64n, k-step 32. 8 warps in 4m x 2n grid, warp tile 32x32.
// A smem pitch 40 bf16 (80B: ldmatrix rows hit distinct banks), W pitch 72.
// ---------------------------------------------------------------------------
__global__ __launch_bounds__(256) void mma_gemm_kernel(
    const __nv_bfloat16* __restrict__ Ahi, const __nv_bfloat16* __restrict__ Alo,
    const __nv_bfloat16* __restrict__ WhiB, const __nv_bfloat16* __restrict__ WloB,
    float* __restrict__ DstB, long long dst_z_stride,
    const float* __restrict__ resid)
{
    __shared__ __nv_bfloat16 sAh[128*40], sAl[128*40], sWh[32*72], sWl[32*72];
    int t = threadIdx.x, w = t >> 5, lane = t & 31;
    int n0 = blockIdx.x * 64, m0 = blockIdx.y * 128, z = blockIdx.z;
    const __nv_bfloat16* Wh = WhiB + (size_t)z * WELEMS;
    const __nv_bfloat16* Wl = WloB + (size_t)z * WELEMS;
    float* Dst = DstB + (size_t)z * dst_z_stride;

    int wm = (w >> 1) * 32, wn = (w & 1) * 32;
    float c[2][4][4];
    #pragma unroll
    for (int i = 0; i < 2; i++)
        #pragma unroll
        for (int j = 0; j < 4; j++)
            #pragma unroll
            for (int k = 0; k < 4; k++) c[i][j][k] = 0.0f;

    unsigned aAh = smem_u32(sAh), aAl = smem_u32(sAl);
    unsigned aWh = smem_u32(sWh), aWl = smem_u32(sWl);

    int lrowA = lane & 15, lkA = (lane >> 4) * 8;          // A ldmatrix lane map
    int lkB = (lane & 7) + ((lane & 8) ? 8 : 0);           // B ldmatrix lane map
    int lnB = (lane & 16) ? 8 : 0;

    int arow = t >> 1, acol = (t & 1) * 16;                // A gmem->smem map
    int wrow = t >> 3, wcol = (t & 7) * 8;                 // W gmem->smem map

    for (int k0 = 0; k0 < DM; k0 += 32) {
        uint4 vah0 = *(const uint4*)&Ahi[(size_t)(m0+arow)*DM + k0 + acol];
        uint4 vah1 = *(const uint4*)&Ahi[(size_t)(m0+arow)*DM + k0 + acol + 8];
        uint4 val0 = *(const uint4*)&Alo[(size_t)(m0+arow)*DM + k0 + acol];
        uint4 val1 = *(const uint4*)&Alo[(size_t)(m0+arow)*DM + k0 + acol + 8];
        uint4 vwh  = *(const uint4*)&Wh[(size_t)(k0+wrow)*DM + n0 + wcol];
        uint4 vwl  = *(const uint4*)&Wl[(size_t)(k0+wrow)*DM + n0 + wcol];
        __syncthreads();   // prior iter's ldmatrix reads complete
        *(uint4*)&sAh[arow*40 + acol]     = vah0;
        *(uint4*)&sAh[arow*40 + acol + 8] = vah1;
        *(uint4*)&sAl[arow*40 + acol]     = val0;
        *(uint4*)&sAl[arow*40 + acol + 8] = val1;
        *(uint4*)&sWh[wrow*72 + wcol] = vwh;
        *(uint4*)&sWl[wrow*72 + wcol] = vwl;
        __syncthreads();

        #pragma unroll
        for (int kk = 0; kk < 32; kk += 16) {
            unsigned ah[2][4], al[2][4], bh[2][4], bl[2][4];
            #pragma unroll
            for (int mf = 0; mf < 2; mf++) {
                unsigned off = (unsigned)((wm + mf*16 + lrowA)*40 + kk + lkA) * 2;
                ldsm4(ah[mf], aAh + off);
                ldsm4(al[mf], aAl + off);
            }
            #pragma unroll
            for (int nh = 0; nh < 2; nh++) {
                unsigned off = (unsigned)((kk + lkB)*72 + wn + nh*16 + lnB) * 2;
                ldsm4t(bh[nh], aWh + off);
                ldsm4t(bl[nh], aWl + off);
            }
            #pragma unroll
            for (int mf = 0; mf < 2; mf++)
                #pragma unroll
                for (int nf = 0; nf < 4; nf++) {
                    unsigned b0h = bh[nf >> 1][(nf & 1)*2], b1h = bh[nf >> 1][(nf & 1)*2 + 1];
                    unsigned b0l = bl[nf >> 1][(nf & 1)*2], b1l = bl[nf >> 1][(nf & 1)*2 + 1];
                    mma16816(c[mf][nf], ah[mf], b0h, b1h);
                    mma16816(c[mf][nf], ah[mf], b0l, b1l);
                    mma16816(c[mf][nf], al[mf], b0h, b1h);
                }
        }
    }

    // epilogue: c frag layout (m16n8): rows g, g+8; cols 2t, 2t+1
    int g = lane >> 2, tc = (lane & 3) * 2;
    #pragma unroll
    for (int mf = 0; mf < 2; mf++)
        #pragma unroll
        for (int nf = 0; nf < 4; nf++) {
            int row = m0 + wm + mf*16 + g;
            int col = n0 + wn + nf*8 + tc;
            float2 v0 = make_float2(c[mf][nf][0], c[mf][nf][1]);
            float2 v1 = make_float2(c[mf][nf][2], c[mf][nf][3]);
            if (resid) {
                float2 r0 = *(const float2*)&resid[(size_t)row*DM + col];
                float2 r1 = *(const float2*)&resid[(size_t)(row+8)*DM + col];
                v0.x += r0.x; v0.y += r0.y; v1.x += r1.x; v1.y += r1.y;
            }
            *(float2*)&Dst[(size_t)row*DM + col] = v0;
            *(float2*)&Dst[(size_t)(row+8)*DM + col] = v1;
        }
}

// ---------------------------------------------------------------------------
// Flash attention (unchanged from round 5 - known good)
// ---------------------------------------------------------------------------
__global__ void attn_kernel(const float* __restrict__ Qbase,
                            const float* __restrict__ Kbase,
                            const float* __restrict__ Vbase,
                            float* __restrict__ Cbase,
                            const float* __restrict__ Bbase) {
    __shared__ float sQ[32 * 68];
    __shared__ float sK[32 * 68];
    __shared__ float sV[32 * 68];
    __shared__ float sP[32 * 33];
    __shared__ float sB[64];

    int t = threadIdx.x;
    int w = t >> 5, c = t & 31;
    int q0 = blockIdx.x << 5;
    int h = blockIdx.y, n = blockIdx.z;
    const float* Qg = Qbase + (size_t)n * SEQ * DM + h * DKV;
    const float* Kg = Kbase + (size_t)n * SEQ * DM + h * DKV;
    const float* Vg = Vbase + (size_t)n * SEQ * DM + h * DKV;
    const float* biasrow = Bbase + h * 4096;

    #pragma unroll
    for (int it = 0; it < 2; it++) {
        int j = t + it * 256;
        int row = j >> 4, d4 = (j & 15) << 2;
        *(float4*)&sQ[row * 68 + d4] = *(const float4*)&Qg[(size_t)(q0 + row) * DM + d4];
    }

    float2 o[4] = {};
    float mrow[4] = {-1e30f, -1e30f, -1e30f, -1e30f};
    float lrow[4] = {};

    for (int k0 = 0; k0 < SEQ; k0 += 32) {
        if (t < 64) sB[t] = biasrow[k0 - q0 + 2016 + t];
        #pragma unroll
        for (int it = 0; it < 2; it++) {
            int j = t + it * 256;
            int row = j >> 4, d4 = (j & 15) << 2;
            *(float4*)&sK[row * 68 + d4] = *(const float4*)&Kg[(size_t)(k0 + row) * DM + d4];
            *(float4*)&sV[row * 68 + d4] = *(const float4*)&Vg[(size_t)(k0 + row) * DM + d4];
        }
        __syncthreads();

        float s[4] = {};
        #pragma unroll
        for (int d4 = 0; d4 < 64; d4 += 4) {
            float4 k4 = *(float4*)&sK[c * 68 + d4];
            #pragma unroll
            for (int r = 0; r < 4; r++) {
                float4 q4 = *(float4*)&sQ[(4 * w + r) * 68 + d4];
                s[r] += q4.x * k4.x + q4.y * k4.y + q4.z * k4.z + q4.w * k4.w;
            }
        }

        #pragma unroll
        for (int r = 0; r < 4; r++) {
            s[r] += sB[c - (4 * w + r) + 31];
            float mx = s[r];
            #pragma unroll
            for (int off = 16; off > 0; off >>= 1)
                mx = fmaxf(mx, __shfl_xor_sync(0xffffffffu, mx, off));
            float mn = fmaxf(mrow[r], mx);
            float alpha = __expf(mrow[r] - mn);
            mrow[r] = mn;
            float p = __expf(s[r] - mn);
            float rs = p;
            #pragma unroll
            for (int off = 16; off > 0; off >>= 1)
                rs += __shfl_xor_sync(0xffffffffu, rs, off);
            lrow[r] = lrow[r] * alpha + rs;
            o[r].x *= alpha; o[r].y *= alpha;
            sP[(4 * w + r) * 33 + c] = p;
        }
        __syncwarp();

        #pragma unroll 4
        for (int k = 0; k < 32; k++) {
            float2 v2 = *(float2*)&sV[k * 68 + 2 * c];
            #pragma unroll
            for (int r = 0; r < 4; r++) {
                float p = sP[(4 * w + r) * 33 + k];
                o[r].x += p * v2.x;
                o[r].y += p * v2.y;
            }
        }
        __syncthreads();
    }

    float* Cg = Cbase + (size_t)n * SEQ * DM + h * DKV;
    #pragma unroll
    for (int r = 0; r < 4; r++) {
        float inv = 1.0f / lrow[r];
        *(float2*)&Cg[(size_t)(q0 + 4 * w + r) * DM + 2 * c] =
            make_float2(o[r].x * inv, o[r].y * inv);
    }
}

// ---------------------------------------------------------------------------
extern "C" void kernel_launch(void* const* d_in, const int* in_sizes, int n_in,
                              void* d_out, int out_size) {
    const float* hidden = (const float*)d_in[0];
    const float* lnw    = (const float*)d_in[1];
    const float* wq     = (const float*)d_in[2];
    const float* wk     = (const float*)d_in[3];
    const float* wv     = (const float*)d_in[4];
    const float* wo     = (const float*)d_in[5];
    const float* table  = (const float*)d_in[6];
    float* out = (float*)d_out;

    // real device addresses of __device__ symbols (NOT host shadows)
    float *pqkv, *pctx, *pbias;
    __nv_bfloat16 *pahi, *palo, *pwhi, *pwlo;
    cudaGetSymbolAddress((void**)&pqkv,  g_qkv);
    cudaGetSymbolAddress((void**)&pctx,  g_ctx);
    cudaGetSymbolAddress((void**)&pbias, g_bias);
    cudaGetSymbolAddress((void**)&pahi,  g_ahi);
    cudaGetSymbolAddress((void**)&palo,  g_alo);
    cudaGetSymbolAddress((void**)&pwhi,  g_whi);
    cudaGetSymbolAddress((void**)&pwlo,  g_wlo);

    bool full = out_size >= (HID_ELEMS + PB_ELEMS + 8);
    float* out_pb     = out + HID_ELEMS;
    float* out_remain = out + HID_ELEMS + PB_ELEMS;

    bias_fill_kernel<<<128, 256>>>(table, full ? out_remain : nullptr);
    if (full) pb_write_kernel<<<dim3(SEQ, NH), 256>>>(out_pb);

    split_w_kernel<<<4*WELEMS/256, 256>>>(wq, wk, wv, wo);
    split_a_kernel<<<ROWS, 128>>>(hidden, lnw);

    // QKV: one launch, z selects weight matrix and destination third
    mma_gemm_kernel<<<dim3(DM/64, ROWS/128, 3), 256>>>(
        pahi, palo, pwhi, pwlo, pqkv, (long long)HID_ELEMS, nullptr);

    attn_kernel<<<dim3(SEQ/32, NH, NBATCH), 256>>>(
        pqkv, pqkv + HID_ELEMS, pqkv + 2*HID_ELEMS, pctx, pbias);

    split_ctx_kernel<<<HID_ELEMS/1024, 256>>>(pctx);

    // output projection + residual
    mma_gemm_kernel<<<dim3(DM/64, ROWS/128, 1), 256>>>(
        pahi, palo, pwhi + 3*WELEMS, pwlo + 3*WELEMS, out, 0, hidden);
}

// round 7
// speedup vs baseline: 2.5662x; 2.1122x over previous
#include <cuda_runtime.h>
#include <cuda_bf16.h>

#define NBATCH 8
#define SEQ 2048
#define DM 512
#define NH 8
#define DKV 64
#define ROWS (NBATCH*SEQ)              // 16384

#define HID_ELEMS (ROWS*DM)            // 8388608
#define PB_ELEMS (NH*SEQ*SEQ)          // 33554432
#define WELEMS (DM*DM)                 // 262144
#define LOG2E 1.4426950408889634f

// scratch (device globals: allocation-free per harness rules)
__device__ float g_bias[NH*4096];            // bias LUT (raw, for pb output)
__device__ float g_bias2[NH*4096];           // bias LUT * log2e (for attention)
__device__ __nv_bfloat16 g_ahi[HID_ELEMS];   // split activations (normed, then ctx)
__device__ __nv_bfloat16 g_alo[HID_ELEMS];
__device__ __nv_bfloat16 g_whi[4*WELEMS];    // wq|wk|wv|wo hi
__device__ __nv_bfloat16 g_wlo[4*WELEMS];
__device__ __nv_bfloat16 g_qkvh[3*HID_ELEMS]; // q|k|v hi (q pre-scaled by log2e)
__device__ __nv_bfloat16 g_qkvl[3*HID_ELEMS]; // lo

// ---------------------------------------------------------------------------
// helpers
// ---------------------------------------------------------------------------
__device__ __forceinline__ unsigned smem_u32(const void* p) {
    unsigned a;
    asm("{ .reg .u64 t; cvta.to.shared.u64 t, %1; cvt.u32.u64 %0, t; }" : "=r"(a) : "l"(p));
    return a;
}
__device__ __forceinline__ void ldsm4(unsigned* r, unsigned addr) {
    asm volatile("ldmatrix.sync.aligned.m8n8.x4.shared.b16 {%0,%1,%2,%3}, [%4];"
        : "=r"(r[0]), "=r"(r[1]), "=r"(r[2]), "=r"(r[3]) : "r"(addr));
}
__device__ __forceinline__ void ldsm4t(unsigned* r, unsigned addr) {
    asm volatile("ldmatrix.sync.aligned.m8n8.x4.trans.shared.b16 {%0,%1,%2,%3}, [%4];"
        : "=r"(r[0]), "=r"(r[1]), "=r"(r[2]), "=r"(r[3]) : "r"(addr));
}
__device__ __forceinline__ void mma16816(float* c, const unsigned* a, unsigned b0, unsigned b1) {
    asm volatile("mma.sync.aligned.m16n8k16.row.col.f32.bf16.bf16.f32 "
        "{%0,%1,%2,%3}, {%4,%5,%6,%7}, {%8,%9}, {%0,%1,%2,%3};"
        : "+f"(c[0]), "+f"(c[1]), "+f"(c[2]), "+f"(c[3])
        : "r"(a[0]), "r"(a[1]), "r"(a[2]), "r"(a[3]), "r"(b0), "r"(b1));
}
__device__ __forceinline__ unsigned pack_bf16x2(float a, float b) {
    unsigned sa = __bfloat16_as_ushort(__float2bfloat16(a));
    unsigned sb = __bfloat16_as_ushort(__float2bfloat16(b));
    return sa | (sb << 16);
}
// hi/lo split of two floats into packed bf16x2 pair
__device__ __forceinline__ void split2(float a, float b, unsigned& uh, unsigned& ul) {
    __nv_bfloat16 ha = __float2bfloat16(a), hb = __float2bfloat16(b);
    uh = (unsigned)__bfloat16_as_ushort(ha) | ((unsigned)__bfloat16_as_ushort(hb) << 16);
    ul = pack_bf16x2(a - __bfloat162float(ha), b - __bfloat162float(hb));
}
// exp2 via magic-constant range reduction + deg-5 Taylor; FMA/ALU pipes, no MUFU
__device__ __forceinline__ float exp2_poly(float y) {
    float t = y + 12582912.0f;                 // 1.5 * 2^23
    int k = __float_as_int(t);                 // low bits hold round(y)
    float f = y - (t - 12582912.0f);           // f in [-0.5, 0.5]
    float p = 1.3333558146e-3f;                //  ln2^5/120
    p = fmaf(p, f, 9.6181291076e-3f);          //  ln2^4/24
    p = fmaf(p, f, 5.5504108664e-2f);          //  ln2^3/6
    p = fmaf(p, f, 2.4022650696e-1f);          //  ln2^2/2
    p = fmaf(p, f, 6.9314718056e-1f);          //  ln2
    p = fmaf(p, f, 1.0f);
    return __int_as_float(__float_as_int(p) + (k << 23));
}

// ---------------------------------------------------------------------------
// Relative-position bias LUTs (exact integer floor of T5 bucket formula)
// ---------------------------------------------------------------------------
__global__ void bias_fill_kernel(const float* __restrict__ table,
                                 float* __restrict__ out_remain) {
    int idx = blockIdx.x * blockDim.x + threadIdx.x;
    if (idx < NH * 4096) {
        int h = idx >> 12;
        int rel = (idx & 4095) - 2047;      // k - q
        int a = rel < 0 ? -rel : rel;
        int b;
        if (a < 8) {
            b = a;
        } else {
            int e = 28 - __clz(a);
            long long aa = (long long)a * (long long)a;
            int v = 2 * e + ((aa >= (1LL << (2 * e + 7))) ? 1 : 0);
            b = 8 + v;
            if (b > 15) b = 15;
        }
        int bucket = (rel > 0 ? 16 : 0) + b;
        float val = table[bucket * NH + h];
        g_bias[idx] = val;
        g_bias2[idx] = val * LOG2E;
    }
    if (out_remain != nullptr && idx < 8) out_remain[idx] = (float)idx;
}

__global__ void pb_write_kernel(float* __restrict__ out_pb) {
    int q = blockIdx.x, h = blockIdx.y;
    const float* brow = g_bias + h * 4096 + (2047 - q);
    float* dst = out_pb + ((size_t)(h * SEQ + q)) * SEQ;
    int t = threadIdx.x;
    #pragma unroll
    for (int it = 0; it < 2; it++) {
        int k4 = (t + it * 256) * 4;
        float4 v = make_float4(brow[k4], brow[k4+1], brow[k4+2], brow[k4+3]);
        *(float4*)&dst[k4] = v;
    }
}

// ---------------------------------------------------------------------------
// Weight split
// ---------------------------------------------------------------------------
__global__ void split_w_kernel(const float* __restrict__ wq, const float* __restrict__ wk,
                               const float* __restrict__ wv, const float* __restrict__ wo) {
    int idx = blockIdx.x * 256 + threadIdx.x;
    const float* src = (idx < WELEMS) ? wq : (idx < 2*WELEMS) ? wk : (idx < 3*WELEMS) ? wv : wo;
    float x = src[idx & (WELEMS - 1)];
    __nv_bfloat16 h = __float2bfloat16(x);
    g_whi[idx] = h;
    g_wlo[idx] = __float2bfloat16(x - __bfloat162float(h));
}

// ---------------------------------------------------------------------------
// Activation split with fused T5 RMS + ln weight
// ---------------------------------------------------------------------------
__global__ void split_a_kernel(const float* __restrict__ hidden, const float* __restrict__ lnw) {
    int m = blockIdx.x, t = threadIdx.x;
    float4 v = *(const float4*)&hidden[(size_t)m * DM + t * 4];
    float s = v.x*v.x + v.y*v.y + v.z*v.z + v.w*v.w;
    #pragma unroll
    for (int off = 16; off > 0; off >>= 1) s += __shfl_xor_sync(0xffffffffu, s, off);
    __shared__ float ws[4];
    if ((t & 31) == 0) ws[t >> 5] = s;
    __syncthreads();
    float rms = rsqrtf((ws[0]+ws[1]+ws[2]+ws[3]) * (1.0f/(float)DM) + 1e-6f);
    float4 l = *(const float4*)&lnw[t * 4];
    float a0 = v.x * l.x * rms, a1 = v.y * l.y * rms;
    float a2 = v.z * l.z * rms, a3 = v.w * l.w * rms;
    unsigned uh0, ul0, uh1, ul1;
    split2(a0, a1, uh0, ul0);
    split2(a2, a3, uh1, ul1);
    *(uint2*)&g_ahi[(size_t)m * DM + t * 4] = make_uint2(uh0, uh1);
    *(uint2*)&g_alo[(size_t)m * DM + t * 4] = make_uint2(ul0, ul1);
}

// ---------------------------------------------------------------------------
// bf16x3 tensor-core GEMM. Two epilogue modes:
//   DstF != 0: fp32 out (+optional resid)
//   else: bf16 hi/lo out (scaled by LOG2E when qkv_mode && z==0)
// ---------------------------------------------------------------------------
__global__ __launch_bounds__(256) void mma_gemm_kernel(
    const __nv_bfloat16* __restrict__ Ahi, const __nv_bfloat16* __restrict__ Alo,
    const __nv_bfloat16* __restrict__ WhiB, const __nv_bfloat16* __restrict__ WloB,
    float* __restrict__ DstF,
    __nv_bfloat16* __restrict__ DstH, __nv_bfloat16* __restrict__ DstL,
    long long dst_z_stride, const float* __restrict__ resid, int qkv_mode)
{
    __shared__ __nv_bfloat16 sAh[128*40], sAl[128*40], sWh[32*72], sWl[32*72];
    int t = threadIdx.x, w = t >> 5, lane = t & 31;
    int n0 = blockIdx.x * 64, m0 = blockIdx.y * 128, z = blockIdx.z;
    const __nv_bfloat16* Wh = WhiB + (size_t)z * WELEMS;
    const __nv_bfloat16* Wl = WloB + (size_t)z * WELEMS;

    int wm = (w >> 1) * 32, wn = (w & 1) * 32;
    float c[2][4][4];
    #pragma unroll
    for (int i = 0; i < 2; i++)
        #pragma unroll
        for (int j = 0; j < 4; j++)
            #pragma unroll
            for (int k = 0; k < 4; k++) c[i][j][k] = 0.0f;

    unsigned aAh = smem_u32(sAh), aAl = smem_u32(sAl);
    unsigned aWh = smem_u32(sWh), aWl = smem_u32(sWl);

    int lrowA = lane & 15, lkA = (lane >> 4) * 8;
    int lkB = (lane & 7) + ((lane & 8) ? 8 : 0);
    int lnB = (lane & 16) ? 8 : 0;

    int arow = t >> 1, acol = (t & 1) * 16;
    int wrow = t >> 3, wcol = (t & 7) * 8;

    for (int k0 = 0; k0 < DM; k0 += 32) {
        uint4 vah0 = *(const uint4*)&Ahi[(size_t)(m0+arow)*DM + k0 + acol];
        uint4 vah1 = *(const uint4*)&Ahi[(size_t)(m0+arow)*DM + k0 + acol + 8];
        uint4 val0 = *(const uint4*)&Alo[(size_t)(m0+arow)*DM + k0 + acol];
        uint4 val1 = *(const uint4*)&Alo[(size_t)(m0+arow)*DM + k0 + acol + 8];
        uint4 vwh  = *(const uint4*)&Wh[(size_t)(k0+wrow)*DM + n0 + wcol];
        uint4 vwl  = *(const uint4*)&Wl[(size_t)(k0+wrow)*DM + n0 + wcol];
        __syncthreads();
        *(uint4*)&sAh[arow*40 + acol]     = vah0;
        *(uint4*)&sAh[arow*40 + acol + 8] = vah1;
        *(uint4*)&sAl[arow*40 + acol]     = val0;
        *(uint4*)&sAl[arow*40 + acol + 8] = val1;
        *(uint4*)&sWh[wrow*72 + wcol] = vwh;
        *(uint4*)&sWl[wrow*72 + wcol] = vwl;
        __syncthreads();

        #pragma unroll
        for (int kk = 0; kk < 32; kk += 16) {
            unsigned ah[2][4], al[2][4], bh[2][4], bl[2][4];
            #pragma unroll
            for (int mf = 0; mf < 2; mf++) {
                unsigned off = (unsigned)((wm + mf*16 + lrowA)*40 + kk + lkA) * 2;
                ldsm4(ah[mf], aAh + off);
                ldsm4(al[mf], aAl + off);
            }
            #pragma unroll
            for (int nh = 0; nh < 2; nh++) {
                unsigned off = (unsigned)((kk + lkB)*72 + wn + nh*16 + lnB) * 2;
                ldsm4t(bh[nh], aWh + off);
                ldsm4t(bl[nh], aWl + off);
            }
            #pragma unroll
            for (int mf = 0; mf < 2; mf++)
                #pragma unroll
                for (int nf = 0; nf < 4; nf++) {
                    unsigned b0h = bh[nf >> 1][(nf & 1)*2], b1h = bh[nf >> 1][(nf & 1)*2 + 1];
                    unsigned b0l = bl[nf >> 1][(nf & 1)*2], b1l = bl[nf >> 1][(nf & 1)*2 + 1];
                    mma16816(c[mf][nf], ah[mf], b0h, b1h);
                    mma16816(c[mf][nf], ah[mf], b0l, b1l);
                    mma16816(c[mf][nf], al[mf], b0h, b1h);
                }
        }
    }

    int g = lane >> 2, tc = (lane & 3) * 2;
    float sc = (qkv_mode && z == 0) ? LOG2E : 1.0f;
    #pragma unroll
    for (int mf = 0; mf < 2; mf++)
        #pragma unroll
        for (int nf = 0; nf < 4; nf++) {
            int row = m0 + wm + mf*16 + g;
            int col = n0 + wn + nf*8 + tc;
            float v0 = c[mf][nf][0] * sc, v1 = c[mf][nf][1] * sc;
            float v2 = c[mf][nf][2] * sc, v3 = c[mf][nf][3] * sc;
            if (DstF) {
                float* Dst = DstF;
                if (resid) {
                    float2 r0 = *(const float2*)&resid[(size_t)row*DM + col];
                    float2 r1 = *(const float2*)&resid[(size_t)(row+8)*DM + col];
                    v0 += r0.x; v1 += r0.y; v2 += r1.x; v3 += r1.y;
                }
                *(float2*)&Dst[(size_t)row*DM + col] = make_float2(v0, v1);
                *(float2*)&Dst[(size_t)(row+8)*DM + col] = make_float2(v2, v3);
            } else {
                size_t zo = (size_t)z * dst_z_stride;
                unsigned uh, ul;
                split2(v0, v1, uh, ul);
                *(unsigned*)&DstH[zo + (size_t)row*DM + col] = uh;
                *(unsigned*)&DstL[zo + (size_t)row*DM + col] = ul;
                split2(v2, v3, uh, ul);
                *(unsigned*)&DstH[zo + (size_t)(row+8)*DM + col] = uh;
                *(unsigned*)&DstL[zo + (size_t)(row+8)*DM + col] = ul;
            }
        }
}

// ---------------------------------------------------------------------------
// Tensor-core flash attention, no online max (scores bounded; 2^y safe in fp32).
// CTA: 128 threads (4 warps), 64 q-rows; k-blocks of 64 keys.
// S = QK^T in log2 domain (Q pre-scaled by log2e), bias LUT pre-scaled.
// exp2 via FMA-pipe polynomial. P built register-locally from S frags.
// Writes ctx as bf16 hi/lo directly into g_ahi/g_alo.
// ---------------------------------------------------------------------------
__global__ __launch_bounds__(128) void attn_mma_kernel(
    const __nv_bfloat16* __restrict__ Qh, const __nv_bfloat16* __restrict__ Ql,
    const __nv_bfloat16* __restrict__ Kh, const __nv_bfloat16* __restrict__ Kl,
    const __nv_bfloat16* __restrict__ Vh, const __nv_bfloat16* __restrict__ Vl,
    __nv_bfloat16* __restrict__ Chi, __nv_bfloat16* __restrict__ Clo,
    const float* __restrict__ Bias2)
{
    __shared__ __nv_bfloat16 sKh[64*72], sKl[64*72], sVh[64*72], sVl[64*72];
    __shared__ float sB[128];

    int t = threadIdx.x, w = t >> 5, lane = t & 31;
    int g = lane >> 2, cq = lane & 3;
    int q0 = blockIdx.x * 64, h = blockIdx.y, n = blockIdx.z;
    size_t base = ((size_t)n * SEQ) * DM + h * DKV;
    const float* brow = Bias2 + h * 4096;

    unsigned aKh = smem_u32(sKh), aKl = smem_u32(sKl);
    unsigned aVh = smem_u32(sVh), aVl = smem_u32(sVl);

    // stage Q tile [64 x 64] hi/lo into sKh/sKl, ldmatrix into regs
    #pragma unroll
    for (int it = 0; it < 4; it++) {
        int slot = t + 128 * it;
        int row = slot >> 3, c8 = (slot & 7) * 8;
        *(uint4*)&sKh[row*72 + c8] = *(const uint4*)&Qh[base + (size_t)(q0+row)*DM + c8];
        *(uint4*)&sKl[row*72 + c8] = *(const uint4*)&Ql[base + (size_t)(q0+row)*DM + c8];
    }
    __syncthreads();
    unsigned qfh[4][4], qfl[4][4];
    #pragma unroll
    for (int kk = 0; kk < 4; kk++) {
        unsigned addr = (unsigned)((16*w + (lane & 15))*72 + 16*kk + ((lane >> 4)*8)) * 2;
        ldsm4(qfh[kk], aKh + addr);
        ldsm4(qfl[kk], aKl + addr);
    }
    __syncthreads();

    float O[8][4];
    #pragma unroll
    for (int j = 0; j < 8; j++)
        #pragma unroll
        for (int e = 0; e < 4; e++) O[j][e] = 0.0f;
    float lac0 = 0.0f, lac1 = 0.0f;

    for (int k0 = 0; k0 < SEQ; k0 += 64) {
        sB[t] = brow[k0 - q0 + 1984 + t];
        #pragma unroll
        for (int it = 0; it < 4; it++) {
            int slot = t + 128 * it;
            int row = slot >> 3, c8 = (slot & 7) * 8;
            size_t go = base + (size_t)(k0+row)*DM + c8;
            *(uint4*)&sKh[row*72 + c8] = *(const uint4*)&Kh[go];
            *(uint4*)&sKl[row*72 + c8] = *(const uint4*)&Kl[go];
            *(uint4*)&sVh[row*72 + c8] = *(const uint4*)&Vh[go];
            *(uint4*)&sVl[row*72 + c8] = *(const uint4*)&Vl[go];
        }
        __syncthreads();

        // ---- S = Q K^T (bf16x3) ----
        float S[8][4];
        #pragma unroll
        for (int j = 0; j < 8; j++)
            #pragma unroll
            for (int e = 0; e < 4; e++) S[j][e] = 0.0f;

        #pragma unroll
        for (int kk = 0; kk < 4; kk++) {
            #pragma unroll
            for (int u = 0; u < 4; u++) {
                unsigned bh[4], bl[4];
                unsigned addr = (unsigned)((16*u + (lane & 7) + ((lane & 16) ? 8 : 0))*72
                                           + 16*kk + ((lane & 8) ? 8 : 0)) * 2;
                ldsm4(bh, aKh + addr);
                ldsm4(bl, aKl + addr);
                #pragma unroll
                for (int jj = 0; jj < 2; jj++) {
                    int j = 2*u + jj;
                    mma16816(S[j], qfh[kk], bh[2*jj], bh[2*jj+1]);
                    mma16816(S[j], qfl[kk], bh[2*jj], bh[2*jj+1]);
                    mma16816(S[j], qfh[kk], bl[2*jj], bl[2*jj+1]);
                }
            }
        }

        // ---- bias + exp2 + split to P frags ----
        unsigned aPh[4][4], aPl[4][4];
        int r0 = 16*w + g;
        #pragma unroll
        for (int j = 0; j < 8; j++) {
            int col = 8*j + 2*cq;
            float p0 = exp2_poly(S[j][0] + sB[col     - r0 + 63]);
            float p1 = exp2_poly(S[j][1] + sB[col + 1 - r0 + 63]);
            float p2 = exp2_poly(S[j][2] + sB[col     - r0 + 55]);
            float p3 = exp2_poly(S[j][3] + sB[col + 1 - r0 + 55]);
            lac0 += p0 + p1;
            lac1 += p2 + p3;
            unsigned uh01, ul01, uh23, ul23;
            split2(p0, p1, uh01, ul01);
            split2(p2, p3, uh23, ul23);
            aPh[j >> 1][(j & 1)*2    ] = uh01;
            aPh[j >> 1][(j & 1)*2 + 1] = uh23;
            aPl[j >> 1][(j & 1)*2    ] = ul01;
            aPl[j >> 1][(j & 1)*2 + 1] = ul23;
        }

        // ---- O += P V (bf16x3) ----
        #pragma unroll
        for (int kkk = 0; kkk < 4; kkk++) {
            #pragma unroll
            for (int u2 = 0; u2 < 4; u2++) {
                unsigned bh[4], bl[4];
                unsigned addr = (unsigned)((16*kkk + (lane & 7) + ((lane & 8) ? 8 : 0))*72
                                           + 16*u2 + ((lane & 16) ? 8 : 0)) * 2;
                ldsm4t(bh, aVh + addr);
                ldsm4t(bl, aVl + addr);
                #pragma unroll
                for (int jj = 0; jj < 2; jj++) {
                    int j = 2*u2 + jj;
                    mma16816(O[j], aPh[kkk], bh[2*jj], bh[2*jj+1]);
                    mma16816(O[j], aPl[kkk], bh[2*jj], bh[2*jj+1]);
                    mma16816(O[j], aPh[kkk], bl[2*jj], bl[2*jj+1]);
                }
            }
        }
        __syncthreads();
    }

    // normalize and write ctx (bf16 hi/lo)
    lac0 += __shfl_xor_sync(0xffffffffu, lac0, 1);
    lac0 += __shfl_xor_sync(0xffffffffu, lac0, 2);
    lac1 += __shfl_xor_sync(0xffffffffu, lac1, 1);
    lac1 += __shfl_xor_sync(0xffffffffu, lac1, 2);
    float li0 = 1.0f / lac0, li1 = 1.0f / lac1;

    size_t rowA = base + (size_t)(q0 + 16*w + g) * DM;
    size_t rowB = base + (size_t)(q0 + 16*w + g + 8) * DM;
    #pragma unroll
    for (int j = 0; j < 8; j++) {
        int col = 8*j + 2*cq;
        unsigned uh, ul;
        split2(O[j][0] * li0, O[j][1] * li0, uh, ul);
        *(unsigned*)&Chi[rowA + col] = uh;
        *(unsigned*)&Clo[rowA + col] = ul;
        split2(O[j][2] * li1, O[j][3] * li1, uh, ul);
        *(unsigned*)&Chi[rowB + col] = uh;
        *(unsigned*)&Clo[rowB + col] = ul;
    }
}

// ---------------------------------------------------------------------------
extern "C" void kernel_launch(void* const* d_in, const int* in_sizes, int n_in,
                              void* d_out, int out_size) {
    const float* hidden = (const float*)d_in[0];
    const float* lnw    = (const float*)d_in[1];
    const float* wq     = (const float*)d_in[2];
    const float* wk     = (const float*)d_in[3];
    const float* wv     = (const float*)d_in[4];
    const float* wo     = (const float*)d_in[5];
    const float* table  = (const float*)d_in[6];
    float* out = (float*)d_out;

    // real device addresses of __device__ symbols (NOT host shadows)
    float *pbias2;
    __nv_bfloat16 *pahi, *palo, *pwhi, *pwlo, *pqh, *pql;
    cudaGetSymbolAddress((void**)&pbias2, g_bias2);
    cudaGetSymbolAddress((void**)&pahi,   g_ahi);
    cudaGetSymbolAddress((void**)&palo,   g_alo);
    cudaGetSymbolAddress((void**)&pwhi,   g_whi);
    cudaGetSymbolAddress((void**)&pwlo,   g_wlo);
    cudaGetSymbolAddress((void**)&pqh,    g_qkvh);
    cudaGetSymbolAddress((void**)&pql,    g_qkvl);

    bool full = out_size >= (HID_ELEMS + PB_ELEMS + 8);
    float* out_pb     = out + HID_ELEMS;
    float* out_remain = out + HID_ELEMS + PB_ELEMS;

    bias_fill_kernel<<<128, 256>>>(table, full ? out_remain : nullptr);
    if (full) pb_write_kernel<<<dim3(SEQ, NH), 256>>>(out_pb);

    split_w_kernel<<<4*WELEMS/256, 256>>>(wq, wk, wv, wo);
    split_a_kernel<<<ROWS, 128>>>(hidden, lnw);

    // QKV projections -> bf16 hi/lo planes (Q scaled by log2e)
    mma_gemm_kernel<<<dim3(DM/64, ROWS/128, 3), 256>>>(
        pahi, palo, pwhi, pwlo, nullptr, pqh, pql,
        (long long)HID_ELEMS, nullptr, 1);

    // attention: ctx -> g_ahi/g_alo (bf16 hi/lo)
    attn_mma_kernel<<<dim3(SEQ/64, NH, NBATCH), 128>>>(
        pqh,                pql,
        pqh +   HID_ELEMS,  pql +   HID_ELEMS,
        pqh + 2*HID_ELEMS,  pql + 2*HID_ELEMS,
        pahi, palo, pbias2);

    // output projection + residual (fp32 out)
    mma_gemm_kernel<<<dim3(DM/64, ROWS/128, 1), 256>>>(
        pahi, palo, pwhi + 3*WELEMS, pwlo + 3*WELEMS, out,
        nullptr, nullptr, 0, hidden, 0);
}

// round 8
// speedup vs baseline: 3.8315x; 1.4931x over previous
#include <cuda_runtime.h>
#include <cuda_bf16.h>

#define NBATCH 8
#define SEQ 2048
#define DM 512
#define NH 8
#define DKV 64
#define ROWS (NBATCH*SEQ)              // 16384

#define HID_ELEMS (ROWS*DM)            // 8388608
#define PB_ELEMS (NH*SEQ*SEQ)          // 33554432
#define WELEMS (DM*DM)                 // 262144
#define LOG2E 1.4426950408889634f

// scratch (device globals: allocation-free per harness rules)
__device__ float g_bias[NH*4096];            // bias LUT (raw, for pb output)
__device__ float g_bias2[NH*4096];           // bias LUT * log2e (for attention)
__device__ __nv_bfloat16 g_ahi[HID_ELEMS];   // split activations (normed, then ctx)
__device__ __nv_bfloat16 g_alo[HID_ELEMS];
__device__ __nv_bfloat16 g_whi[4*WELEMS];    // wq|wk|wv|wo hi
__device__ __nv_bfloat16 g_wlo[4*WELEMS];
__device__ __nv_bfloat16 g_qkvh[3*HID_ELEMS]; // q|k|v hi (q pre-scaled by log2e)
__device__ __nv_bfloat16 g_qkvl[3*HID_ELEMS]; // lo

// ---------------------------------------------------------------------------
// helpers
// ---------------------------------------------------------------------------
__device__ __forceinline__ unsigned smem_u32(const void* p) {
    unsigned a;
    asm("{ .reg .u64 t; cvta.to.shared.u64 t, %1; cvt.u32.u64 %0, t; }" : "=r"(a) : "l"(p));
    return a;
}
__device__ __forceinline__ void ldsm4(unsigned* r, unsigned addr) {
    asm volatile("ldmatrix.sync.aligned.m8n8.x4.shared.b16 {%0,%1,%2,%3}, [%4];"
        : "=r"(r[0]), "=r"(r[1]), "=r"(r[2]), "=r"(r[3]) : "r"(addr));
}
__device__ __forceinline__ void ldsm4t(unsigned* r, unsigned addr) {
    asm volatile("ldmatrix.sync.aligned.m8n8.x4.trans.shared.b16 {%0,%1,%2,%3}, [%4];"
        : "=r"(r[0]), "=r"(r[1]), "=r"(r[2]), "=r"(r[3]) : "r"(addr));
}
__device__ __forceinline__ void mma16816(float* c, const unsigned* a, unsigned b0, unsigned b1) {
    asm volatile("mma.sync.aligned.m16n8k16.row.col.f32.bf16.bf16.f32 "
        "{%0,%1,%2,%3}, {%4,%5,%6,%7}, {%8,%9}, {%0,%1,%2,%3};"
        : "+f"(c[0]), "+f"(c[1]), "+f"(c[2]), "+f"(c[3])
        : "r"(a[0]), "r"(a[1]), "r"(a[2]), "r"(a[3]), "r"(b0), "r"(b1));
}
__device__ __forceinline__ void cp16(unsigned saddr, const void* g) {
    asm volatile("cp.async.ca.shared.global [%0], [%1], 16;" :: "r"(saddr), "l"(g));
}
#define CP_COMMIT() asm volatile("cp.async.commit_group;")
#define CP_WAIT(N)  asm volatile("cp.async.wait_group %0;" :: "n"(N))

__device__ __forceinline__ unsigned pack_bf16x2(float a, float b) {
    unsigned sa = __bfloat16_as_ushort(__float2bfloat16(a));
    unsigned sb = __bfloat16_as_ushort(__float2bfloat16(b));
    return sa | (sb << 16);
}
__device__ __forceinline__ void split2(float a, float b, unsigned& uh, unsigned& ul) {
    __nv_bfloat16 ha = __float2bfloat16(a), hb = __float2bfloat16(b);
    uh = (unsigned)__bfloat16_as_ushort(ha) | ((unsigned)__bfloat16_as_ushort(hb) << 16);
    ul = pack_bf16x2(a - __bfloat162float(ha), b - __bfloat162float(hb));
}
// exp2 via magic-constant range reduction + deg-5 Taylor; FMA/ALU pipes, no MUFU
__device__ __forceinline__ float exp2_poly(float y) {
    float t = y + 12582912.0f;                 // 1.5 * 2^23
    int k = __float_as_int(t);
    float f = y - (t - 12582912.0f);
    float p = 1.3333558146e-3f;
    p = fmaf(p, f, 9.6181291076e-3f);
    p = fmaf(p, f, 5.5504108664e-2f);
    p = fmaf(p, f, 2.4022650696e-1f);
    p = fmaf(p, f, 6.9314718056e-1f);
    p = fmaf(p, f, 1.0f);
    return __int_as_float(__float_as_int(p) + (k << 23));
}

// ---------------------------------------------------------------------------
// Relative-position bias LUTs (exact integer floor of T5 bucket formula)
// ---------------------------------------------------------------------------
__global__ void bias_fill_kernel(const float* __restrict__ table,
                                 float* __restrict__ out_remain) {
    int idx = blockIdx.x * blockDim.x + threadIdx.x;
    if (idx < NH * 4096) {
        int h = idx >> 12;
        int rel = (idx & 4095) - 2047;      // k - q
        int a = rel < 0 ? -rel : rel;
        int b;
        if (a < 8) {
            b = a;
        } else {
            int e = 28 - __clz(a);
            long long aa = (long long)a * (long long)a;
            int v = 2 * e + ((aa >= (1LL << (2 * e + 7))) ? 1 : 0);
            b = 8 + v;
            if (b > 15) b = 15;
        }
        int bucket = (rel > 0 ? 16 : 0) + b;
        float val = table[bucket * NH + h];
        g_bias[idx] = val;
        g_bias2[idx] = val * LOG2E;
    }
    if (out_remain != nullptr && idx < 8) out_remain[idx] = (float)idx;
}

__global__ void pb_write_kernel(float* __restrict__ out_pb) {
    int q = blockIdx.x, h = blockIdx.y;
    const float* brow = g_bias + h * 4096 + (2047 - q);
    float* dst = out_pb + ((size_t)(h * SEQ + q)) * SEQ;
    int t = threadIdx.x;
    #pragma unroll
    for (int it = 0; it < 2; it++) {
        int k4 = (t + it * 256) * 4;
        float4 v = make_float4(brow[k4], brow[k4+1], brow[k4+2], brow[k4+3]);
        *(float4*)&dst[k4] = v;
    }
}

// ---------------------------------------------------------------------------
// Weight split
// ---------------------------------------------------------------------------
__global__ void split_w_kernel(const float* __restrict__ wq, const float* __restrict__ wk,
                               const float* __restrict__ wv, const float* __restrict__ wo) {
    int idx = blockIdx.x * 256 + threadIdx.x;
    const float* src = (idx < WELEMS) ? wq : (idx < 2*WELEMS) ? wk : (idx < 3*WELEMS) ? wv : wo;
    float x = src[idx & (WELEMS - 1)];
    __nv_bfloat16 h = __float2bfloat16(x);
    g_whi[idx] = h;
    g_wlo[idx] = __float2bfloat16(x - __bfloat162float(h));
}

// ---------------------------------------------------------------------------
// Activation split with fused T5 RMS + ln weight
// ---------------------------------------------------------------------------
__global__ void split_a_kernel(const float* __restrict__ hidden, const float* __restrict__ lnw) {
    int m = blockIdx.x, t = threadIdx.x;
    float4 v = *(const float4*)&hidden[(size_t)m * DM + t * 4];
    float s = v.x*v.x + v.y*v.y + v.z*v.z + v.w*v.w;
    #pragma unroll
    for (int off = 16; off > 0; off >>= 1) s += __shfl_xor_sync(0xffffffffu, s, off);
    __shared__ float ws[4];
    if ((t & 31) == 0) ws[t >> 5] = s;
    __syncthreads();
    float rms = rsqrtf((ws[0]+ws[1]+ws[2]+ws[3]) * (1.0f/(float)DM) + 1e-6f);
    float4 l = *(const float4*)&lnw[t * 4];
    float a0 = v.x * l.x * rms, a1 = v.y * l.y * rms;
    float a2 = v.z * l.z * rms, a3 = v.w * l.w * rms;
    unsigned uh0, ul0, uh1, ul1;
    split2(a0, a1, uh0, ul0);
    split2(a2, a3, uh1, ul1);
    *(uint2*)&g_ahi[(size_t)m * DM + t * 4] = make_uint2(uh0, uh1);
    *(uint2*)&g_alo[(size_t)m * DM + t * 4] = make_uint2(ul0, ul1);
}

// ---------------------------------------------------------------------------
// bf16x3 tensor-core GEMM (unchanged, known-good)
// ---------------------------------------------------------------------------
__global__ __launch_bounds__(256) void mma_gemm_kernel(
    const __nv_bfloat16* __restrict__ Ahi, const __nv_bfloat16* __restrict__ Alo,
    const __nv_bfloat16* __restrict__ WhiB, const __nv_bfloat16* __restrict__ WloB,
    float* __restrict__ DstF,
    __nv_bfloat16* __restrict__ DstH, __nv_bfloat16* __restrict__ DstL,
    long long dst_z_stride, const float* __restrict__ resid, int qkv_mode)
{
    __shared__ __nv_bfloat16 sAh[128*40], sAl[128*40], sWh[32*72], sWl[32*72];
    int t = threadIdx.x, w = t >> 5, lane = t & 31;
    int n0 = blockIdx.x * 64, m0 = blockIdx.y * 128, z = blockIdx.z;
    const __nv_bfloat16* Wh = WhiB + (size_t)z * WELEMS;
    const __nv_bfloat16* Wl = WloB + (size_t)z * WELEMS;

    int wm = (w >> 1) * 32, wn = (w & 1) * 32;
    float c[2][4][4];
    #pragma unroll
    for (int i = 0; i < 2; i++)
        #pragma unroll
        for (int j = 0; j < 4; j++)
            #pragma unroll
            for (int k = 0; k < 4; k++) c[i][j][k] = 0.0f;

    unsigned aAh = smem_u32(sAh), aAl = smem_u32(sAl);
    unsigned aWh = smem_u32(sWh), aWl = smem_u32(sWl);

    int lrowA = lane & 15, lkA = (lane >> 4) * 8;
    int lkB = (lane & 7) + ((lane & 8) ? 8 : 0);
    int lnB = (lane & 16) ? 8 : 0;

    int arow = t >> 1, acol = (t & 1) * 16;
    int wrow = t >> 3, wcol = (t & 7) * 8;

    for (int k0 = 0; k0 < DM; k0 += 32) {
        uint4 vah0 = *(const uint4*)&Ahi[(size_t)(m0+arow)*DM + k0 + acol];
        uint4 vah1 = *(const uint4*)&Ahi[(size_t)(m0+arow)*DM + k0 + acol + 8];
        uint4 val0 = *(const uint4*)&Alo[(size_t)(m0+arow)*DM + k0 + acol];
        uint4 val1 = *(const uint4*)&Alo[(size_t)(m0+arow)*DM + k0 + acol + 8];
        uint4 vwh  = *(const uint4*)&Wh[(size_t)(k0+wrow)*DM + n0 + wcol];
        uint4 vwl  = *(const uint4*)&Wl[(size_t)(k0+wrow)*DM + n0 + wcol];
        __syncthreads();
        *(uint4*)&sAh[arow*40 + acol]     = vah0;
        *(uint4*)&sAh[arow*40 + acol + 8] = vah1;
        *(uint4*)&sAl[arow*40 + acol]     = val0;
        *(uint4*)&sAl[arow*40 + acol + 8] = val1;
        *(uint4*)&sWh[wrow*72 + wcol] = vwh;
        *(uint4*)&sWl[wrow*72 + wcol] = vwl;
        __syncthreads();

        #pragma unroll
        for (int kk = 0; kk < 32; kk += 16) {
            unsigned ah[2][4], al[2][4], bh[2][4], bl[2][4];
            #pragma unroll
            for (int mf = 0; mf < 2; mf++) {
                unsigned off = (unsigned)((wm + mf*16 + lrowA)*40 + kk + lkA) * 2;
                ldsm4(ah[mf], aAh + off);
                ldsm4(al[mf], aAl + off);
            }
            #pragma unroll
            for (int nh = 0; nh < 2; nh++) {
                unsigned off = (unsigned)((kk + lkB)*72 + wn + nh*16 + lnB) * 2;
                ldsm4t(bh[nh], aWh + off);
                ldsm4t(bl[nh], aWl + off);
            }
            #pragma unroll
            for (int mf = 0; mf < 2; mf++)
                #pragma unroll
                for (int nf = 0; nf < 4; nf++) {
                    unsigned b0h = bh[nf >> 1][(nf & 1)*2], b1h = bh[nf >> 1][(nf & 1)*2 + 1];
                    unsigned b0l = bl[nf >> 1][(nf & 1)*2], b1l = bl[nf >> 1][(nf & 1)*2 + 1];
                    mma16816(c[mf][nf], ah[mf], b0h, b1h);
                    mma16816(c[mf][nf], ah[mf], b0l, b1l);
                    mma16816(c[mf][nf], al[mf], b0h, b1h);
                }
        }
    }

    int g = lane >> 2, tc = (lane & 3) * 2;
    float sc = (qkv_mode && z == 0) ? LOG2E : 1.0f;
    #pragma unroll
    for (int mf = 0; mf < 2; mf++)
        #pragma unroll
        for (int nf = 0; nf < 4; nf++) {
            int row = m0 + wm + mf*16 + g;
            int col = n0 + wn + nf*8 + tc;
            float v0 = c[mf][nf][0] * sc, v1 = c[mf][nf][1] * sc;
            float v2 = c[mf][nf][2] * sc, v3 = c[mf][nf][3] * sc;
            if (DstF) {
                float* Dst = DstF;
                if (resid) {
                    float2 r0 = *(const float2*)&resid[(size_t)row*DM + col];
                    float2 r1 = *(const float2*)&resid[(size_t)(row+8)*DM + col];
                    v0 += r0.x; v1 += r0.y; v2 += r1.x; v3 += r1.y;
                }
                *(float2*)&Dst[(size_t)row*DM + col] = make_float2(v0, v1);
                *(float2*)&Dst[(size_t)(row+8)*DM + col] = make_float2(v2, v3);
            } else {
                size_t zo = (size_t)z * dst_z_stride;
                unsigned uh, ul;
                split2(v0, v1, uh, ul);
                *(unsigned*)&DstH[zo + (size_t)row*DM + col] = uh;
                *(unsigned*)&DstL[zo + (size_t)row*DM + col] = ul;
                split2(v2, v3, uh, ul);
                *(unsigned*)&DstH[zo + (size_t)(row+8)*DM + col] = uh;
                *(unsigned*)&DstL[zo + (size_t)(row+8)*DM + col] = ul;
            }
        }
}

// ---------------------------------------------------------------------------
// Tensor-core flash attention v2:
//   - 128 q-rows per CTA (256 threads, 8 warps; warp w owns rows 16w..16w+15)
//   - 2-stage cp.async pipeline on K/V (double-buffered dynamic smem)
//   - no online max (scores bounded; 2^y safe in fp32), exp2 on FMA pipe
// Dynamic smem: 2 stages x 4 planes (Kh,Kl,Vh,Vl) of [64][72] bf16 + bias[2][192]
// ---------------------------------------------------------------------------
#define ATT_PLANE (64*72)                    // bf16 elems per plane
#define ATT_STAGE_B (4*ATT_PLANE*2)          // 36864 bytes per stage
#define ATT_SMEM_B (2*ATT_STAGE_B + 2*192*4) // 75264 bytes

__global__ __launch_bounds__(256) void attn_mma_kernel(
    const __nv_bfloat16* __restrict__ Qh, const __nv_bfloat16* __restrict__ Ql,
    const __nv_bfloat16* __restrict__ Kh, const __nv_bfloat16* __restrict__ Kl,
    const __nv_bfloat16* __restrict__ Vh, const __nv_bfloat16* __restrict__ Vl,
    __nv_bfloat16* __restrict__ Chi, __nv_bfloat16* __restrict__ Clo,
    const float* __restrict__ Bias2)
{
    extern __shared__ char dyns[];
    __nv_bfloat16* sKV = (__nv_bfloat16*)dyns;         // 2 stages
    float* sB = (float*)(dyns + 2*ATT_STAGE_B);        // [2][192]

    int t = threadIdx.x, w = t >> 5, lane = t & 31;
    int g = lane >> 2, cq = lane & 3;
    int q0 = blockIdx.x * 128, h = blockIdx.y, n = blockIdx.z;
    size_t base = ((size_t)n * SEQ) * DM + h * DKV;
    const float* brow = Bias2 + h * 4096;

    unsigned sbase = smem_u32(dyns);

    // ---- Q prologue: stage [128][72] hi/lo into stage area, ldmatrix frags ----
    {
        __nv_bfloat16* Qs_h = sKV;                      // 128*72 elems
        __nv_bfloat16* Qs_l = sKV + 128*72;
        #pragma unroll
        for (int it = 0; it < 4; it++) {
            int slot = t + 256*it;                      // 1024 slots
            int row = slot >> 3, c8 = (slot & 7) * 8;
            *(uint4*)&Qs_h[row*72 + c8] = *(const uint4*)&Qh[base + (size_t)(q0+row)*DM + c8];
            *(uint4*)&Qs_l[row*72 + c8] = *(const uint4*)&Ql[base + (size_t)(q0+row)*DM + c8];
        }
    }
    __syncthreads();
    unsigned qfh[4][4], qfl[4][4];
    unsigned aQh = sbase, aQl = sbase + 128*72*2;
    #pragma unroll
    for (int kk = 0; kk < 4; kk++) {
        unsigned addr = (unsigned)((16*w + (lane & 15))*72 + 16*kk + ((lane >> 4)*8)) * 2;
        ldsm4(qfh[kk], aQh + addr);
        ldsm4(qfl[kk], aQl + addr);
    }
    __syncthreads();

    float O[8][4];
    #pragma unroll
    for (int j = 0; j < 8; j++)
        #pragma unroll
        for (int e = 0; e < 4; e++) O[j][e] = 0.0f;
    float lac0 = 0.0f, lac1 = 0.0f;

    const int NB = SEQ / 64;

    // prefetch of k-block kb into stage st
    #define ATT_PREFETCH(kb, st) do {                                            \
        int k0_ = (kb) * 64;                                                     \
        unsigned sst = sbase + (unsigned)(st) * ATT_STAGE_B;                     \
        _Pragma("unroll")                                                        \
        for (int it = 0; it < 2; it++) {                                         \
            int slot = t + 256*it;                                               \
            int row = slot >> 3, c8 = (slot & 7) * 8;                            \
            unsigned so = (unsigned)(row*72 + c8) * 2;                           \
            size_t go = base + (size_t)(k0_ + row)*DM + c8;                      \
            cp16(sst + so,                    &Kh[go]);                          \
            cp16(sst + ATT_PLANE*2   + so,    &Kl[go]);                          \
            cp16(sst + ATT_PLANE*4   + so,    &Vh[go]);                          \
            cp16(sst + ATT_PLANE*6   + so,    &Vl[go]);                          \
        }                                                                        \
        if (t < 192) sB[(st)*192 + t] = brow[k0_ - q0 + 1920 + t];               \
        CP_COMMIT();                                                             \
    } while (0)

    ATT_PREFETCH(0, 0);

    for (int kb = 0; kb < NB; kb++) {
        int st = kb & 1;
        if (kb + 1 < NB) {
            ATT_PREFETCH(kb + 1, st ^ 1);
            CP_WAIT(1);
        } else {
            CP_WAIT(0);
        }
        __syncthreads();

        unsigned aKh = sbase + (unsigned)st * ATT_STAGE_B;
        unsigned aKl = aKh + ATT_PLANE*2;
        unsigned aVh = aKh + ATT_PLANE*4;
        unsigned aVl = aKh + ATT_PLANE*6;
        const float* sBc = sB + st*192;

        // ---- S = Q K^T (bf16x3) ----
        float S[8][4];
        #pragma unroll
        for (int j = 0; j < 8; j++)
            #pragma unroll
            for (int e = 0; e < 4; e++) S[j][e] = 0.0f;

        #pragma unroll
        for (int kk = 0; kk < 4; kk++) {
            #pragma unroll
            for (int u = 0; u < 4; u++) {
                unsigned bh[4], bl[4];
                unsigned addr = (unsigned)((16*u + (lane & 7) + ((lane & 16) ? 8 : 0))*72
                                           + 16*kk + ((lane & 8) ? 8 : 0)) * 2;
                ldsm4(bh, aKh + addr);
                ldsm4(bl, aKl + addr);
                #pragma unroll
                for (int jj = 0; jj < 2; jj++) {
                    int j = 2*u + jj;
                    mma16816(S[j], qfh[kk], bh[2*jj], bh[2*jj+1]);
                    mma16816(S[j], qfl[kk], bh[2*jj], bh[2*jj+1]);
                    mma16816(S[j], qfh[kk], bl[2*jj], bl[2*jj+1]);
                }
            }
        }

        // ---- bias + exp2 + split to P frags ----
        unsigned aPh[4][4], aPl[4][4];
        int r0 = 16*w + g;
        #pragma unroll
        for (int j = 0; j < 8; j++) {
            int col = 8*j + 2*cq;
            float p0 = exp2_poly(S[j][0] + sBc[col     - r0 + 127]);
            float p1 = exp2_poly(S[j][1] + sBc[col + 1 - r0 + 127]);
            float p2 = exp2_poly(S[j][2] + sBc[col     - r0 + 119]);
            float p3 = exp2_poly(S[j][3] + sBc[col + 1 - r0 + 119]);
            lac0 += p0 + p1;
            lac1 += p2 + p3;
            unsigned uh01, ul01, uh23, ul23;
            split2(p0, p1, uh01, ul01);
            split2(p2, p3, uh23, ul23);
            aPh[j >> 1][(j & 1)*2    ] = uh01;
            aPh[j >> 1][(j & 1)*2 + 1] = uh23;
            aPl[j >> 1][(j & 1)*2    ] = ul01;
            aPl[j >> 1][(j & 1)*2 + 1] = ul23;
        }

        // ---- O += P V (bf16x3) ----
        #pragma unroll
        for (int kkk = 0; kkk < 4; kkk++) {
            #pragma unroll
            for (int u2 = 0; u2 < 4; u2++) {
                unsigned bh[4], bl[4];
                unsigned addr = (unsigned)((16*kkk + (lane & 7) + ((lane & 8) ? 8 : 0))*72
                                           + 16*u2 + ((lane & 16) ? 8 : 0)) * 2;
                ldsm4t(bh, aVh + addr);
                ldsm4t(bl, aVl + addr);
                #pragma unroll
                for (int jj = 0; jj < 2; jj++) {
                    int j = 2*u2 + jj;
                    mma16816(O[j], aPh[kkk], bh[2*jj], bh[2*jj+1]);
                    mma16816(O[j], aPl[kkk], bh[2*jj], bh[2*jj+1]);
                    mma16816(O[j], aPh[kkk], bl[2*jj], bl[2*jj+1]);
                }
            }
        }
        __syncthreads();   // all warps done reading stage st before it is refilled
    }

    // normalize and write ctx (bf16 hi/lo)
    lac0 += __shfl_xor_sync(0xffffffffu, lac0, 1);
    lac0 += __shfl_xor_sync(0xffffffffu, lac0, 2);
    lac1 += __shfl_xor_sync(0xffffffffu, lac1, 1);
    lac1 += __shfl_xor_sync(0xffffffffu, lac1, 2);
    float li0 = 1.0f / lac0, li1 = 1.0f / lac1;

    size_t rowA = base + (size_t)(q0 + 16*w + g) * DM;
    size_t rowB = base + (size_t)(q0 + 16*w + g + 8) * DM;
    #pragma unroll
    for (int j = 0; j < 8; j++) {
        int col = 8*j + 2*cq;
        unsigned uh, ul;
        split2(O[j][0] * li0, O[j][1] * li0, uh, ul);
        *(unsigned*)&Chi[rowA + col] = uh;
        *(unsigned*)&Clo[rowA + col] = ul;
        split2(O[j][2] * li1, O[j][3] * li1, uh, ul);
        *(unsigned*)&Chi[rowB + col] = uh;
        *(unsigned*)&Clo[rowB + col] = ul;
    }
}

// ---------------------------------------------------------------------------
extern "C" void kernel_launch(void* const* d_in, const int* in_sizes, int n_in,
                              void* d_out, int out_size) {
    const float* hidden = (const float*)d_in[0];
    const float* lnw    = (const float*)d_in[1];
    const float* wq     = (const float*)d_in[2];
    const float* wk     = (const float*)d_in[3];
    const float* wv     = (const float*)d_in[4];
    const float* wo     = (const float*)d_in[5];
    const float* table  = (const float*)d_in[6];
    float* out = (float*)d_out;

    // real device addresses of __device__ symbols (NOT host shadows)
    float *pbias2;
    __nv_bfloat16 *pahi, *palo, *pwhi, *pwlo, *pqh, *pql;
    cudaGetSymbolAddress((void**)&pbias2, g_bias2);
    cudaGetSymbolAddress((void**)&pahi,   g_ahi);
    cudaGetSymbolAddress((void**)&palo,   g_alo);
    cudaGetSymbolAddress((void**)&pwhi,   g_whi);
    cudaGetSymbolAddress((void**)&pwlo,   g_wlo);
    cudaGetSymbolAddress((void**)&pqh,    g_qkvh);
    cudaGetSymbolAddress((void**)&pql,    g_qkvl);

    cudaFuncSetAttribute(attn_mma_kernel,
                         cudaFuncAttributeMaxDynamicSharedMemorySize, ATT_SMEM_B);

    bool full = out_size >= (HID_ELEMS + PB_ELEMS + 8);
    float* out_pb     = out + HID_ELEMS;
    float* out_remain = out + HID_ELEMS + PB_ELEMS;

    bias_fill_kernel<<<128, 256>>>(table, full ? out_remain : nullptr);
    if (full) pb_write_kernel<<<dim3(SEQ, NH), 256>>>(out_pb);

    split_w_kernel<<<4*WELEMS/256, 256>>>(wq, wk, wv, wo);
    split_a_kernel<<<ROWS, 128>>>(hidden, lnw);

    // QKV projections -> bf16 hi/lo planes (Q scaled by log2e)
    mma_gemm_kernel<<<dim3(DM/64, ROWS/128, 3), 256>>>(
        pahi, palo, pwhi, pwlo, nullptr, pqh, pql,
        (long long)HID_ELEMS, nullptr, 1);

    // attention: ctx -> g_ahi/g_alo (bf16 hi/lo)
    attn_mma_kernel<<<dim3(SEQ/128, NH, NBATCH), 256, ATT_SMEM_B>>>(
        pqh,                pql,
        pqh +   HID_ELEMS,  pql +   HID_ELEMS,
        pqh + 2*HID_ELEMS,  pql + 2*HID_ELEMS,
        pahi, palo, pbias2);

    // output projection + residual (fp32 out)
    mma_gemm_kernel<<<dim3(DM/64, ROWS/128, 1), 256>>>(
        pahi, palo, pwhi + 3*WELEMS, pwlo + 3*WELEMS, out,
        nullptr, nullptr, 0, hidden, 0);
}

// round 9
// speedup vs baseline: 4.1334x; 1.0788x over previous
#include <cuda_runtime.h>
#include <cuda_bf16.h>

#define NBATCH 8
#define SEQ 2048
#define DM 512
#define NH 8
#define DKV 64
#define ROWS (NBATCH*SEQ)              // 16384

#define HID_ELEMS (ROWS*DM)            // 8388608
#define PB_ELEMS (NH*SEQ*SEQ)          // 33554432
#define WELEMS (DM*DM)                 // 262144
#define LOG2E 1.4426950408889634f

// scratch (device globals: allocation-free per harness rules)
__device__ float g_bias[NH*4096];            // bias LUT (raw, for pb output)
__device__ float g_bias2[NH*4096];           // bias LUT * log2e (for attention)
__device__ __nv_bfloat16 g_ahi[HID_ELEMS];   // split activations (normed, then ctx)
__device__ __nv_bfloat16 g_alo[HID_ELEMS];
__device__ __nv_bfloat16 g_whi[4*WELEMS];    // wq|wk|wv|wo hi
__device__ __nv_bfloat16 g_wlo[4*WELEMS];
__device__ __nv_bfloat16 g_qkvh[3*HID_ELEMS]; // q|k|v hi (q pre-scaled by log2e)
__device__ __nv_bfloat16 g_qkvl[3*HID_ELEMS]; // lo

// ---------------------------------------------------------------------------
// helpers
// ---------------------------------------------------------------------------
__device__ __forceinline__ unsigned smem_u32(const void* p) {
    unsigned a;
    asm("{ .reg .u64 t; cvta.to.shared.u64 t, %1; cvt.u32.u64 %0, t; }" : "=r"(a) : "l"(p));
    return a;
}
__device__ __forceinline__ void ldsm4(unsigned* r, unsigned addr) {
    asm volatile("ldmatrix.sync.aligned.m8n8.x4.shared.b16 {%0,%1,%2,%3}, [%4];"
        : "=r"(r[0]), "=r"(r[1]), "=r"(r[2]), "=r"(r[3]) : "r"(addr));
}
__device__ __forceinline__ void ldsm4t(unsigned* r, unsigned addr) {
    asm volatile("ldmatrix.sync.aligned.m8n8.x4.trans.shared.b16 {%0,%1,%2,%3}, [%4];"
        : "=r"(r[0]), "=r"(r[1]), "=r"(r[2]), "=r"(r[3]) : "r"(addr));
}
__device__ __forceinline__ void mma16816(float* c, const unsigned* a, unsigned b0, unsigned b1) {
    asm volatile("mma.sync.aligned.m16n8k16.row.col.f32.bf16.bf16.f32 "
        "{%0,%1,%2,%3}, {%4,%5,%6,%7}, {%8,%9}, {%0,%1,%2,%3};"
        : "+f"(c[0]), "+f"(c[1]), "+f"(c[2]), "+f"(c[3])
        : "r"(a[0]), "r"(a[1]), "r"(a[2]), "r"(a[3]), "r"(b0), "r"(b1));
}
__device__ __forceinline__ void cp16(unsigned saddr, const void* g) {
    asm volatile("cp.async.ca.shared.global [%0], [%1], 16;" :: "r"(saddr), "l"(g));
}
#define CP_COMMIT() asm volatile("cp.async.commit_group;")
#define CP_WAIT(N)  asm volatile("cp.async.wait_group %0;" :: "n"(N))

__device__ __forceinline__ unsigned pack_bf16x2(float a, float b) {
    unsigned sa = __bfloat16_as_ushort(__float2bfloat16(a));
    unsigned sb = __bfloat16_as_ushort(__float2bfloat16(b));
    return sa | (sb << 16);
}
__device__ __forceinline__ void split2(float a, float b, unsigned& uh, unsigned& ul) {
    __nv_bfloat16 ha = __float2bfloat16(a), hb = __float2bfloat16(b);
    uh = (unsigned)__bfloat16_as_ushort(ha) | ((unsigned)__bfloat16_as_ushort(hb) << 16);
    ul = pack_bf16x2(a - __bfloat162float(ha), b - __bfloat162float(hb));
}
// exp2 via magic-constant range reduction + deg-5 Taylor; FMA/ALU pipes, no MUFU
__device__ __forceinline__ float exp2_poly(float y) {
    float t = y + 12582912.0f;                 // 1.5 * 2^23
    int k = __float_as_int(t);
    float f = y - (t - 12582912.0f);
    float p = 1.3333558146e-3f;
    p = fmaf(p, f, 9.6181291076e-3f);
    p = fmaf(p, f, 5.5504108664e-2f);
    p = fmaf(p, f, 2.4022650696e-1f);
    p = fmaf(p, f, 6.9314718056e-1f);
    p = fmaf(p, f, 1.0f);
    return __int_as_float(__float_as_int(p) + (k << 23));
}

// ---------------------------------------------------------------------------
// Relative-position bias LUTs (exact integer floor of T5 bucket formula)
// ---------------------------------------------------------------------------
__global__ void bias_fill_kernel(const float* __restrict__ table,
                                 float* __restrict__ out_remain) {
    int idx = blockIdx.x * blockDim.x + threadIdx.x;
    if (idx < NH * 4096) {
        int h = idx >> 12;
        int rel = (idx & 4095) - 2047;      // k - q
        int a = rel < 0 ? -rel : rel;
        int b;
        if (a < 8) {
            b = a;
        } else {
            int e = 28 - __clz(a);
            long long aa = (long long)a * (long long)a;
            int v = 2 * e + ((aa >= (1LL << (2 * e + 7))) ? 1 : 0);
            b = 8 + v;
            if (b > 15) b = 15;
        }
        int bucket = (rel > 0 ? 16 : 0) + b;
        float val = table[bucket * NH + h];
        g_bias[idx] = val;
        g_bias2[idx] = val * LOG2E;
    }
    if (out_remain != nullptr && idx < 8) out_remain[idx] = (float)idx;
}

__global__ void pb_write_kernel(float* __restrict__ out_pb) {
    int q = blockIdx.x, h = blockIdx.y;
    const float* brow = g_bias + h * 4096 + (2047 - q);
    float* dst = out_pb + ((size_t)(h * SEQ + q)) * SEQ;
    int t = threadIdx.x;
    #pragma unroll
    for (int it = 0; it < 2; it++) {
        int k4 = (t + it * 256) * 4;
        float4 v = make_float4(brow[k4], brow[k4+1], brow[k4+2], brow[k4+3]);
        *(float4*)&dst[k4] = v;
    }
}

// ---------------------------------------------------------------------------
// Weight split
// ---------------------------------------------------------------------------
__global__ void split_w_kernel(const float* __restrict__ wq, const float* __restrict__ wk,
                               const float* __restrict__ wv, const float* __restrict__ wo) {
    int idx = blockIdx.x * 256 + threadIdx.x;
    const float* src = (idx < WELEMS) ? wq : (idx < 2*WELEMS) ? wk : (idx < 3*WELEMS) ? wv : wo;
    float x = src[idx & (WELEMS - 1)];
    __nv_bfloat16 h = __float2bfloat16(x);
    g_whi[idx] = h;
    g_wlo[idx] = __float2bfloat16(x - __bfloat162float(h));
}

// ---------------------------------------------------------------------------
// Activation split with fused T5 RMS + ln weight
// ---------------------------------------------------------------------------
__global__ void split_a_kernel(const float* __restrict__ hidden, const float* __restrict__ lnw) {
    int m = blockIdx.x, t = threadIdx.x;
    float4 v = *(const float4*)&hidden[(size_t)m * DM + t * 4];
    float s = v.x*v.x + v.y*v.y + v.z*v.z + v.w*v.w;
    #pragma unroll
    for (int off = 16; off > 0; off >>= 1) s += __shfl_xor_sync(0xffffffffu, s, off);
    __shared__ float ws[4];
    if ((t & 31) == 0) ws[t >> 5] = s;
    __syncthreads();
    float rms = rsqrtf((ws[0]+ws[1]+ws[2]+ws[3]) * (1.0f/(float)DM) + 1e-6f);
    float4 l = *(const float4*)&lnw[t * 4];
    float a0 = v.x * l.x * rms, a1 = v.y * l.y * rms;
    float a2 = v.z * l.z * rms, a3 = v.w * l.w * rms;
    unsigned uh0, ul0, uh1, ul1;
    split2(a0, a1, uh0, ul0);
    split2(a2, a3, uh1, ul1);
    *(uint2*)&g_ahi[(size_t)m * DM + t * 4] = make_uint2(uh0, uh1);
    *(uint2*)&g_alo[(size_t)m * DM + t * 4] = make_uint2(ul0, ul1);
}

// ---------------------------------------------------------------------------
// bf16x3 tensor-core GEMM with 2-stage cp.async pipeline (same pattern as
// the attention kernel). CTA tile 128m x 64n, k-step 32.
// Dynamic smem: 2 stages x { Ahi,Alo [128][40] + Whi,Wlo [32][72] } bf16.
// ---------------------------------------------------------------------------
#define G_APITCH 40
#define G_WPITCH 72
#define G_A_PLANE (128*G_APITCH)               // 5120 elems
#define G_W_PLANE (32*G_WPITCH)                // 2304 elems
#define G_STAGE_B ((2*G_A_PLANE + 2*G_W_PLANE)*2)   // 29696 bytes
#define G_SMEM_B (2*G_STAGE_B)                 // 59392 bytes

__global__ __launch_bounds__(256) void mma_gemm_kernel(
    const __nv_bfloat16* __restrict__ Ahi, const __nv_bfloat16* __restrict__ Alo,
    const __nv_bfloat16* __restrict__ WhiB, const __nv_bfloat16* __restrict__ WloB,
    float* __restrict__ DstF,
    __nv_bfloat16* __restrict__ DstH, __nv_bfloat16* __restrict__ DstL,
    long long dst_z_stride, const float* __restrict__ resid, int qkv_mode)
{
    extern __shared__ char gs[];
    unsigned sbase = smem_u32(gs);

    int t = threadIdx.x, w = t >> 5, lane = t & 31;
    int n0 = blockIdx.x * 64, m0 = blockIdx.y * 128, z = blockIdx.z;
    const __nv_bfloat16* Wh = WhiB + (size_t)z * WELEMS;
    const __nv_bfloat16* Wl = WloB + (size_t)z * WELEMS;

    int wm = (w >> 1) * 32, wn = (w & 1) * 32;
    float c[2][4][4];
    #pragma unroll
    for (int i = 0; i < 2; i++)
        #pragma unroll
        for (int j = 0; j < 4; j++)
            #pragma unroll
            for (int k = 0; k < 4; k++) c[i][j][k] = 0.0f;

    int lrowA = lane & 15, lkA = (lane >> 4) * 8;
    int lkB = (lane & 7) + ((lane & 8) ? 8 : 0);
    int lnB = (lane & 16) ? 8 : 0;

    // prefetch of k-step k0_ into stage st
    #define GEMM_PREFETCH(k0_, st) do {                                          \
        unsigned sA_h = sbase + (unsigned)(st) * G_STAGE_B;                      \
        unsigned sA_l = sA_h + G_A_PLANE*2;                                      \
        unsigned sW_h = sA_l + G_A_PLANE*2;                                      \
        unsigned sW_l = sW_h + G_W_PLANE*2;                                      \
        _Pragma("unroll")                                                        \
        for (int it = 0; it < 2; it++) {                                         \
            int slot = t + 256*it;            /* 512 slots: 128 rows x 4 c8 */   \
            int row = slot >> 2, c8 = (slot & 3) * 8;                            \
            unsigned so = (unsigned)(row*G_APITCH + c8) * 2;                     \
            size_t go = (size_t)(m0 + row)*DM + (k0_) + c8;                      \
            cp16(sA_h + so, &Ahi[go]);                                           \
            cp16(sA_l + so, &Alo[go]);                                           \
        }                                                                        \
        {                                                                        \
            int row = t >> 3, c8 = (t & 7) * 8;   /* 256 slots: 32 x 8 */        \
            unsigned so = (unsigned)(row*G_WPITCH + c8) * 2;                     \
            size_t go = (size_t)((k0_) + row)*DM + n0 + c8;                      \
            cp16(sW_h + so, &Wh[go]);                                            \
            cp16(sW_l + so, &Wl[go]);                                            \
        }                                                                        \
        CP_COMMIT();                                                             \
    } while (0)

    GEMM_PREFETCH(0, 0);

    const int NK = DM / 32;   // 16
    for (int ks = 0; ks < NK; ks++) {
        int st = ks & 1;
        if (ks + 1 < NK) {
            GEMM_PREFETCH((ks + 1) * 32, st ^ 1);
            CP_WAIT(1);
        } else {
            CP_WAIT(0);
        }
        __syncthreads();

        unsigned aAh = sbase + (unsigned)st * G_STAGE_B;
        unsigned aAl = aAh + G_A_PLANE*2;
        unsigned aWh = aAl + G_A_PLANE*2;
        unsigned aWl = aWh + G_W_PLANE*2;

        #pragma unroll
        for (int kk = 0; kk < 32; kk += 16) {
            unsigned ah[2][4], al[2][4], bh[2][4], bl[2][4];
            #pragma unroll
            for (int mf = 0; mf < 2; mf++) {
                unsigned off = (unsigned)((wm + mf*16 + lrowA)*G_APITCH + kk + lkA) * 2;
                ldsm4(ah[mf], aAh + off);
                ldsm4(al[mf], aAl + off);
            }
            #pragma unroll
            for (int nh = 0; nh < 2; nh++) {
                unsigned off = (unsigned)((kk + lkB)*G_WPITCH + wn + nh*16 + lnB) * 2;
                ldsm4t(bh[nh], aWh + off);
                ldsm4t(bl[nh], aWl + off);
            }
            #pragma unroll
            for (int mf = 0; mf < 2; mf++)
                #pragma unroll
                for (int nf = 0; nf < 4; nf++) {
                    unsigned b0h = bh[nf >> 1][(nf & 1)*2], b1h = bh[nf >> 1][(nf & 1)*2 + 1];
                    unsigned b0l = bl[nf >> 1][(nf & 1)*2], b1l = bl[nf >> 1][(nf & 1)*2 + 1];
                    mma16816(c[mf][nf], ah[mf], b0h, b1h);
                    mma16816(c[mf][nf], ah[mf], b0l, b1l);
                    mma16816(c[mf][nf], al[mf], b0h, b1h);
                }
        }
        __syncthreads();   // stage st fully consumed before it is refilled
    }

    int g = lane >> 2, tc = (lane & 3) * 2;
    float sc = (qkv_mode && z == 0) ? LOG2E : 1.0f;
    #pragma unroll
    for (int mf = 0; mf < 2; mf++)
        #pragma unroll
        for (int nf = 0; nf < 4; nf++) {
            int row = m0 + wm + mf*16 + g;
            int col = n0 + wn + nf*8 + tc;
            float v0 = c[mf][nf][0] * sc, v1 = c[mf][nf][1] * sc;
            float v2 = c[mf][nf][2] * sc, v3 = c[mf][nf][3] * sc;
            if (DstF) {
                float* Dst = DstF;
                if (resid) {
                    float2 r0 = *(const float2*)&resid[(size_t)row*DM + col];
                    float2 r1 = *(const float2*)&resid[(size_t)(row+8)*DM + col];
                    v0 += r0.x; v1 += r0.y; v2 += r1.x; v3 += r1.y;
                }
                *(float2*)&Dst[(size_t)row*DM + col] = make_float2(v0, v1);
                *(float2*)&Dst[(size_t)(row+8)*DM + col] = make_float2(v2, v3);
            } else {
                size_t zo = (size_t)z * dst_z_stride;
                unsigned uh, ul;
                split2(v0, v1, uh, ul);
                *(unsigned*)&DstH[zo + (size_t)row*DM + col] = uh;
                *(unsigned*)&DstL[zo + (size_t)row*DM + col] = ul;
                split2(v2, v3, uh, ul);
                *(unsigned*)&DstH[zo + (size_t)(row+8)*DM + col] = uh;
                *(unsigned*)&DstL[zo + (size_t)(row+8)*DM + col] = ul;
            }
        }
}

// ---------------------------------------------------------------------------
// Tensor-core flash attention v2 (unchanged from round 8 — known good):
//   - 128 q-rows per CTA (256 threads, 8 warps; warp w owns rows 16w..16w+15)
//   - 2-stage cp.async pipeline on K/V (double-buffered dynamic smem)
//   - no online max (scores bounded; 2^y safe in fp32), exp2 on FMA pipe
// ---------------------------------------------------------------------------
#define ATT_PLANE (64*72)                    // bf16 elems per plane
#define ATT_STAGE_B (4*ATT_PLANE*2)          // 36864 bytes per stage
#define ATT_SMEM_B (2*ATT_STAGE_B + 2*192*4) // 75264 bytes

__global__ __launch_bounds__(256) void attn_mma_kernel(
    const __nv_bfloat16* __restrict__ Qh, const __nv_bfloat16* __restrict__ Ql,
    const __nv_bfloat16* __restrict__ Kh, const __nv_bfloat16* __restrict__ Kl,
    const __nv_bfloat16* __restrict__ Vh, const __nv_bfloat16* __restrict__ Vl,
    __nv_bfloat16* __restrict__ Chi, __nv_bfloat16* __restrict__ Clo,
    const float* __restrict__ Bias2)
{
    extern __shared__ char dyns[];
    __nv_bfloat16* sKV = (__nv_bfloat16*)dyns;         // 2 stages
    float* sB = (float*)(dyns + 2*ATT_STAGE_B);        // [2][192]

    int t = threadIdx.x, w = t >> 5, lane = t & 31;
    int g = lane >> 2, cq = lane & 3;
    int q0 = blockIdx.x * 128, h = blockIdx.y, n = blockIdx.z;
    size_t base = ((size_t)n * SEQ) * DM + h * DKV;
    const float* brow = Bias2 + h * 4096;

    unsigned sbase = smem_u32(dyns);

    // ---- Q prologue: stage [128][72] hi/lo into stage area, ldmatrix frags ----
    {
        __nv_bfloat16* Qs_h = sKV;
        __nv_bfloat16* Qs_l = sKV + 128*72;
        #pragma unroll
        for (int it = 0; it < 4; it++) {
            int slot = t + 256*it;
            int row = slot >> 3, c8 = (slot & 7) * 8;
            *(uint4*)&Qs_h[row*72 + c8] = *(const uint4*)&Qh[base + (size_t)(q0+row)*DM + c8];
            *(uint4*)&Qs_l[row*72 + c8] = *(const uint4*)&Ql[base + (size_t)(q0+row)*DM + c8];
        }
    }
    __syncthreads();
    unsigned qfh[4][4], qfl[4][4];
    unsigned aQh = sbase, aQl = sbase + 128*72*2;
    #pragma unroll
    for (int kk = 0; kk < 4; kk++) {
        unsigned addr = (unsigned)((16*w + (lane & 15))*72 + 16*kk + ((lane >> 4)*8)) * 2;
        ldsm4(qfh[kk], aQh + addr);
        ldsm4(qfl[kk], aQl + addr);
    }
    __syncthreads();

    float O[8][4];
    #pragma unroll
    for (int j = 0; j < 8; j++)
        #pragma unroll
        for (int e = 0; e < 4; e++) O[j][e] = 0.0f;
    float lac0 = 0.0f, lac1 = 0.0f;

    const int NB = SEQ / 64;

    #define ATT_PREFETCH(kb, st) do {                                            \
        int k0_ = (kb) * 64;                                                     \
        unsigned sst = sbase + (unsigned)(st) * ATT_STAGE_B;                     \
        _Pragma("unroll")                                                        \
        for (int it = 0; it < 2; it++) {                                         \
            int slot = t + 256*it;                                               \
            int row = slot >> 3, c8 = (slot & 7) * 8;                            \
            unsigned so = (unsigned)(row*72 + c8) * 2;                           \
            size_t go = base + (size_t)(k0_ + row)*DM + c8;                      \
            cp16(sst + so,                    &Kh[go]);                          \
            cp16(sst + ATT_PLANE*2   + so,    &Kl[go]);                          \
            cp16(sst + ATT_PLANE*4   + so,    &Vh[go]);                          \
            cp16(sst + ATT_PLANE*6   + so,    &Vl[go]);                          \
        }                                                                        \
        if (t < 192) sB[(st)*192 + t] = brow[k0_ - q0 + 1920 + t];               \
        CP_COMMIT();                                                             \
    } while (0)

    ATT_PREFETCH(0, 0);

    for (int kb = 0; kb < NB; kb++) {
        int st = kb & 1;
        if (kb + 1 < NB) {
            ATT_PREFETCH(kb + 1, st ^ 1);
            CP_WAIT(1);
        } else {
            CP_WAIT(0);
        }
        __syncthreads();

        unsigned aKh = sbase + (unsigned)st * ATT_STAGE_B;
        unsigned aKl = aKh + ATT_PLANE*2;
        unsigned aVh = aKh + ATT_PLANE*4;
        unsigned aVl = aKh + ATT_PLANE*6;
        const float* sBc = sB + st*192;

        // ---- S = Q K^T (bf16x3) ----
        float S[8][4];
        #pragma unroll
        for (int j = 0; j < 8; j++)
            #pragma unroll
            for (int e = 0; e < 4; e++) S[j][e] = 0.0f;

        #pragma unroll
        for (int kk = 0; kk < 4; kk++) {
            #pragma unroll
            for (int u = 0; u < 4; u++) {
                unsigned bh[4], bl[4];
                unsigned addr = (unsigned)((16*u + (lane & 7) + ((lane & 16) ? 8 : 0))*72
                                           + 16*kk + ((lane & 8) ? 8 : 0)) * 2;
                ldsm4(bh, aKh + addr);
                ldsm4(bl, aKl + addr);
                #pragma unroll
                for (int jj = 0; jj < 2; jj++) {
                    int j = 2*u + jj;
                    mma16816(S[j], qfh[kk], bh[2*jj], bh[2*jj+1]);
                    mma16816(S[j], qfl[kk], bh[2*jj], bh[2*jj+1]);
                    mma16816(S[j], qfh[kk], bl[2*jj], bl[2*jj+1]);
                }
            }
        }

        // ---- bias + exp2 + split to P frags ----
        unsigned aPh[4][4], aPl[4][4];
        int r0 = 16*w + g;
        #pragma unroll
        for (int j = 0; j < 8; j++) {
            int col = 8*j + 2*cq;
            float p0 = exp2_poly(S[j][0] + sBc[col     - r0 + 127]);
            float p1 = exp2_poly(S[j][1] + sBc[col + 1 - r0 + 127]);
            float p2 = exp2_poly(S[j][2] + sBc[col     - r0 + 119]);
            float p3 = exp2_poly(S[j][3] + sBc[col + 1 - r0 + 119]);
            lac0 += p0 + p1;
            lac1 += p2 + p3;
            unsigned uh01, ul01, uh23, ul23;
            split2(p0, p1, uh01, ul01);
            split2(p2, p3, uh23, ul23);
            aPh[j >> 1][(j & 1)*2    ] = uh01;
            aPh[j >> 1][(j & 1)*2 + 1] = uh23;
            aPl[j >> 1][(j & 1)*2    ] = ul01;
            aPl[j >> 1][(j & 1)*2 + 1] = ul23;
        }

        // ---- O += P V (bf16x3) ----
        #pragma unroll
        for (int kkk = 0; kkk < 4; kkk++) {
            #pragma unroll
            for (int u2 = 0; u2 < 4; u2++) {
                unsigned bh[4], bl[4];
                unsigned addr = (unsigned)((16*kkk + (lane & 7) + ((lane & 8) ? 8 : 0))*72
                                           + 16*u2 + ((lane & 16) ? 8 : 0)) * 2;
                ldsm4t(bh, aVh + addr);
                ldsm4t(bl, aVl + addr);
                #pragma unroll
                for (int jj = 0; jj < 2; jj++) {
                    int j = 2*u2 + jj;
                    mma16816(O[j], aPh[kkk], bh[2*jj], bh[2*jj+1]);
                    mma16816(O[j], aPl[kkk], bh[2*jj], bh[2*jj+1]);
                    mma16816(O[j], aPh[kkk], bl[2*jj], bl[2*jj+1]);
                }
            }
        }
        __syncthreads();
    }

    // normalize and write ctx (bf16 hi/lo)
    lac0 += __shfl_xor_sync(0xffffffffu, lac0, 1);
    lac0 += __shfl_xor_sync(0xffffffffu, lac0, 2);
    lac1 += __shfl_xor_sync(0xffffffffu, lac1, 1);
    lac1 += __shfl_xor_sync(0xffffffffu, lac1, 2);
    float li0 = 1.0f / lac0, li1 = 1.0f / lac1;

    size_t rowA = base + (size_t)(q0 + 16*w + g) * DM;
    size_t rowB = base + (size_t)(q0 + 16*w + g + 8) * DM;
    #pragma unroll
    for (int j = 0; j < 8; j++) {
        int col = 8*j + 2*cq;
        unsigned uh, ul;
        split2(O[j][0] * li0, O[j][1] * li0, uh, ul);
        *(unsigned*)&Chi[rowA + col] = uh;
        *(unsigned*)&Clo[rowA + col] = ul;
        split2(O[j][2] * li1, O[j][3] * li1, uh, ul);
        *(unsigned*)&Chi[rowB + col] = uh;
        *(unsigned*)&Clo[rowB + col] = ul;
    }
}

// ---------------------------------------------------------------------------
extern "C" void kernel_launch(void* const* d_in, const int* in_sizes, int n_in,
                              void* d_out, int out_size) {
    const float* hidden = (const float*)d_in[0];
    const float* lnw    = (const float*)d_in[1];
    const float* wq     = (const float*)d_in[2];
    const float* wk     = (const float*)d_in[3];
    const float* wv     = (const float*)d_in[4];
    const float* wo     = (const float*)d_in[5];
    const float* table  = (const float*)d_in[6];
    float* out = (float*)d_out;

    // real device addresses of __device__ symbols (NOT host shadows)
    float *pbias2;
    __nv_bfloat16 *pahi, *palo, *pwhi, *pwlo, *pqh, *pql;
    cudaGetSymbolAddress((void**)&pbias2, g_bias2);
    cudaGetSymbolAddress((void**)&pahi,   g_ahi);
    cudaGetSymbolAddress((void**)&palo,   g_alo);
    cudaGetSymbolAddress((void**)&pwhi,   g_whi);
    cudaGetSymbolAddress((void**)&pwlo,   g_wlo);
    cudaGetSymbolAddress((void**)&pqh,    g_qkvh);
    cudaGetSymbolAddress((void**)&pql,    g_qkvl);

    cudaFuncSetAttribute(attn_mma_kernel,
                         cudaFuncAttributeMaxDynamicSharedMemorySize, ATT_SMEM_B);
    cudaFuncSetAttribute(mma_gemm_kernel,
                         cudaFuncAttributeMaxDynamicSharedMemorySize, G_SMEM_B);

    bool full = out_size >= (HID_ELEMS + PB_ELEMS + 8);
    float* out_pb     = out + HID_ELEMS;
    float* out_remain = out + HID_ELEMS + PB_ELEMS;

    bias_fill_kernel<<<128, 256>>>(table, full ? out_remain : nullptr);
    if (full) pb_write_kernel<<<dim3(SEQ, NH), 256>>>(out_pb);

    split_w_kernel<<<4*WELEMS/256, 256>>>(wq, wk, wv, wo);
    split_a_kernel<<<ROWS, 128>>>(hidden, lnw);

    // QKV projections -> bf16 hi/lo planes (Q scaled by log2e)
    mma_gemm_kernel<<<dim3(DM/64, ROWS/128, 3), 256, G_SMEM_B>>>(
        pahi, palo, pwhi, pwlo, nullptr, pqh, pql,
        (long long)HID_ELEMS, nullptr, 1);

    // attention: ctx -> g_ahi/g_alo (bf16 hi/lo)
    attn_mma_kernel<<<dim3(SEQ/128, NH, NBATCH), 256, ATT_SMEM_B>>>(
        pqh,                pql,
        pqh +   HID_ELEMS,  pql +   HID_ELEMS,
        pqh + 2*HID_ELEMS,  pql + 2*HID_ELEMS,
        pahi, palo, pbias2);

    // output projection + residual (fp32 out)
    mma_gemm_kernel<<<dim3(DM/64, ROWS/128, 1), 256, G_SMEM_B>>>(
        pahi, palo, pwhi + 3*WELEMS, pwlo + 3*WELEMS, out,
        nullptr, nullptr, 0, hidden, 0);
}